// round 11
// baseline (speedup 1.0000x reference)
#include <cuda_runtime.h>
#include <cuda_fp16.h>
#include <cstdint>

// Problem constants
#define NB    16
#define CD    256
#define HH    80
#define WW    60
#define LL    4800            // HH*WW
#define NHD   8
#define HDD   32
#define MR    (NB*LL)         // 76800 rows

#define EPI_NONE 0
#define EPI_ELU1 1
#define EPI_RELU 2

// ---------------- scratch (static device globals; no allocation) ----------------
__device__ float  g_F0 [(size_t)MR * CD];    // exact x (residual/output)
__device__ __half g_F0h[(size_t)MR * CD];
__device__ __half g_F1h[(size_t)MR * CD];
__device__ __half g_Qh [(size_t)MR * CD];
__device__ __half g_Kh [(size_t)MR * CD];
__device__ __half g_Vh [(size_t)MR * CD];
__device__ float  g_PE [(size_t)CD * LL];
__device__ float  g_KV [NB * NHD * HDD * HDD];
__device__ float  g_KS [NB * NHD * HDD];
// fp16 weights, TRANSPOSED: WT[n*K + k] = W[k][n]  (k contiguous)
__device__ __half g_WqH[2 * CD * CD];
__device__ __half g_WkH[2 * CD * CD];
__device__ __half g_WvH[2 * CD * CD];
__device__ __half g_WmH[2 * CD * CD];
__device__ __half g_W1H[2 * 2 * CD * CD];    // [256 n][512 k] per layer
__device__ __half g_W2H[2 * CD * CD];

// ---------------- weight prep: fp16 + transpose to [N][K] ----------------
__global__ void weight_prep_kernel(
    const float* __restrict__ wq, const float* __restrict__ wk,
    const float* __restrict__ wv, const float* __restrict__ wm,
    const float* __restrict__ w1, const float* __restrict__ w2)
{
    int i = blockIdx.x * blockDim.x + threadIdx.x;
    const int S = 2 * CD * CD;              // 131072
    if (i < S) {
        int li = i >> 16;                   // CD*CD = 65536
        int r  = i & 65535;
        int k = r >> 8, n = r & 255;
        int dst = li * 65536 + n * 256 + k;
        g_WqH[dst] = __float2half_rn(wq[i]);
        g_WkH[dst] = __float2half_rn(wk[i]);
        g_WvH[dst] = __float2half_rn(wv[i]);
        g_WmH[dst] = __float2half_rn(wm[i]);
        g_W2H[dst] = __float2half_rn(w2[i]);
    }
    if (i < 2 * S) {                        // W1: [512 k][256 n] per layer
        int li = i >> 17;                   // 131072 per layer
        int r  = i & 131071;
        int k = r >> 8, n = r & 255;
        int dst = li * 131072 + n * 512 + k;
        g_W1H[dst] = __float2half_rn(w1[i]);
    }
}

// ---------------- positional encoding ----------------
// fac = (-log(1e4)/256)//2 == -1.0  =>  div[j] = exp(-2*j)
__global__ void pe_precompute_kernel(float* __restrict__ PE) {
    int idx = blockIdx.x * blockDim.x + threadIdx.x;
    if (idx >= CD * LL) return;
    int c = idx / LL, l = idx % LL;
    int j = c >> 2, r = c & 3;
    int h = l / WW, w = l % WW;
    float f = expf(-2.0f * (float)j);
    float pos = (r < 2) ? (float)(w + 1) : (float)(h + 1);
    float arg = pos * f;
    PE[idx] = (r & 1) ? cosf(arg) : sinf(arg);
}

// NCHW -> [N,L,C] with PE; writes optional f32 + fp16
__global__ void build_pe_kernel(const float* __restrict__ feat, const float* __restrict__ PE,
                                float* __restrict__ outF, __half* __restrict__ outH) {
    __shared__ float tile[32][33];
    int n  = blockIdx.z;
    int c0 = blockIdx.y * 32;
    int l0 = blockIdx.x * 32;
    int tx = threadIdx.x, ty = threadIdx.y;
#pragma unroll
    for (int i = 0; i < 4; i++) {
        int c = c0 + ty + i * 8;
        int l = l0 + tx;
        tile[ty + i * 8][tx] = feat[((size_t)n * CD + c) * LL + l] + PE[(size_t)c * LL + l];
    }
    __syncthreads();
#pragma unroll
    for (int i = 0; i < 4; i++) {
        int l = l0 + ty + i * 8;
        int c = c0 + tx;
        float v = tile[tx][ty + i * 8];
        size_t o = ((size_t)n * LL + l) * CD + c;
        if (outF) outF[o] = v;
        outH[o] = __float2half_rn(v);
    }
}

__global__ void unbuild_kernel(const float* __restrict__ in, float* __restrict__ out) {
    __shared__ float tile[32][33];
    int n  = blockIdx.z;
    int c0 = blockIdx.y * 32;
    int l0 = blockIdx.x * 32;
    int tx = threadIdx.x, ty = threadIdx.y;
#pragma unroll
    for (int i = 0; i < 4; i++) {
        int l = l0 + ty + i * 8;
        int c = c0 + tx;
        tile[ty + i * 8][tx] = in[((size_t)n * LL + l) * CD + c];
    }
    __syncthreads();
#pragma unroll
    for (int i = 0; i < 4; i++) {
        int c = c0 + ty + i * 8;
        int l = l0 + tx;
        out[((size_t)n * CD + c) * LL + l] = tile[tx][ty + i * 8];
    }
}

// ---------------- helpers ----------------
__device__ __forceinline__ void cp16(void* dst, const void* src) {
    uint32_t d = (uint32_t)__cvta_generic_to_shared(dst);
    asm volatile("cp.async.cg.shared.global [%0], [%1], 16;\n" :: "r"(d), "l"(src));
}
__device__ __forceinline__ void ldsm4(uint32_t& r0, uint32_t& r1, uint32_t& r2, uint32_t& r3,
                                      uint32_t addr) {
    asm volatile("ldmatrix.sync.aligned.m8n8.x4.shared.b16 {%0,%1,%2,%3}, [%4];"
                 : "=r"(r0), "=r"(r1), "=r"(r2), "=r"(r3) : "r"(addr));
}

// ---------------- FP16 tensor-core GEMM (m16n8k16, f32 accum, ldmatrix) ----------------
// C[M,N] = epi( [A|A2][M,Ktot] @ WT^T ), A row-major fp16, WT[n][k] fp16 (k contig).
// BM=BN=128, BK=16, 8 warps, warp tile 32x64.
// SMEM: rows of 16 halves at stride RSW=12 words (48B) -> ldmatrix conflict-free.
#define RSW 12
#define AS_WORDS (128 * RSW)
#define BS_WORDS (128 * RSW)

__global__ __launch_bounds__(256, 2) void hgemm_kernel(
    const __half* __restrict__ A, const __half* __restrict__ A2,
    const __half* __restrict__ B, void* __restrict__ Cout,
    int M, int Ktot, int K1, int N, int epi, int outHalf)
{
    __shared__ uint32_t As2[2][AS_WORDS];
    __shared__ uint32_t Bs2[2][BS_WORDS];

    int tid = threadIdx.x;
    int warp = tid >> 5;
    int lane = tid & 31;
    int g = lane >> 2;
    int q = lane & 3;
    int rowBase = blockIdx.y * 128;
    int colBase = blockIdx.x * 128;
    int wm0 = (warp >> 1) * 32;
    int wn0 = (warp & 1) * 64;
    int K2 = Ktot - K1;
    int NS = Ktot >> 4;

    float acc[2][8][4];
#pragma unroll
    for (int mt = 0; mt < 2; mt++)
#pragma unroll
        for (int nt = 0; nt < 8; nt++)
#pragma unroll
            for (int r = 0; r < 4; r++) acc[mt][nt][r] = 0.0f;

    // fill: 256 chunks each for A and B: row = tid>>1, half j = tid&1
    int fRow = tid >> 1, fJ = tid & 1;

    auto issue = [&](int s, int buf) {
        int k0 = s << 4;
        int kk = k0 + fJ * 8;
        const __half* srcA = (kk < K1)
            ? (A  + (size_t)(rowBase + fRow) * K1 + kk)
            : (A2 + (size_t)(rowBase + fRow) * K2 + (kk - K1));
        cp16(&As2[buf][fRow * RSW + fJ * 4], srcA);
        cp16(&Bs2[buf][fRow * RSW + fJ * 4],
             B + (size_t)(colBase + fRow) * Ktot + k0 + fJ * 8);
    };

    // ldmatrix per-lane word offsets
    int aOffW = (wm0 + (lane & 15)) * RSW + (lane >> 4) * 4;
    int bOffW = (wn0 + (lane & 7) + ((lane >> 4) << 3)) * RSW + ((lane >> 3) & 1) * 4;

    issue(0, 0);
    asm volatile("cp.async.commit_group;\n");

    int buf = 0;
    for (int s = 0; s < NS; s++) {
        if (s + 1 < NS) {
            issue(s + 1, buf ^ 1);
            asm volatile("cp.async.commit_group;\n");
            asm volatile("cp.async.wait_group 1;\n");
        } else {
            asm volatile("cp.async.wait_group 0;\n");
        }
        __syncthreads();

        uint32_t asBase = (uint32_t)__cvta_generic_to_shared(&As2[buf][0]);
        uint32_t bsBase = (uint32_t)__cvta_generic_to_shared(&Bs2[buf][0]);

        uint32_t af[2][4];
        ldsm4(af[0][0], af[0][1], af[0][2], af[0][3], asBase + aOffW * 4);
        ldsm4(af[1][0], af[1][1], af[1][2], af[1][3], asBase + (aOffW + 16 * RSW) * 4);
        uint32_t bf[8][2];
#pragma unroll
        for (int i = 0; i < 4; i++)
            ldsm4(bf[2*i][0], bf[2*i][1], bf[2*i+1][0], bf[2*i+1][1],
                  bsBase + (bOffW + i * 16 * RSW) * 4);

#pragma unroll
        for (int mt = 0; mt < 2; mt++)
#pragma unroll
            for (int nt = 0; nt < 8; nt++) {
                asm volatile(
                    "mma.sync.aligned.m16n8k16.row.col.f32.f16.f16.f32 "
                    "{%0,%1,%2,%3}, {%4,%5,%6,%7}, {%8,%9}, {%0,%1,%2,%3};\n"
                    : "+f"(acc[mt][nt][0]), "+f"(acc[mt][nt][1]),
                      "+f"(acc[mt][nt][2]), "+f"(acc[mt][nt][3])
                    : "r"(af[mt][0]), "r"(af[mt][1]), "r"(af[mt][2]), "r"(af[mt][3]),
                      "r"(bf[nt][0]), "r"(bf[nt][1]));
            }
        buf ^= 1;
        __syncthreads();
    }

#pragma unroll
    for (int mt = 0; mt < 2; mt++) {
        int row = rowBase + wm0 + mt * 16 + g;
#pragma unroll
        for (int nt = 0; nt < 8; nt++) {
            int col = colBase + wn0 + nt * 8 + 2 * q;
            float v0 = acc[mt][nt][0], v1 = acc[mt][nt][1];
            float v2 = acc[mt][nt][2], v3 = acc[mt][nt][3];
            if (epi == EPI_ELU1) {
                v0 = (v0 > 0.f) ? v0 + 1.f : expf(v0);
                v1 = (v1 > 0.f) ? v1 + 1.f : expf(v1);
                v2 = (v2 > 0.f) ? v2 + 1.f : expf(v2);
                v3 = (v3 > 0.f) ? v3 + 1.f : expf(v3);
            } else if (epi == EPI_RELU) {
                v0 = fmaxf(v0, 0.f); v1 = fmaxf(v1, 0.f);
                v2 = fmaxf(v2, 0.f); v3 = fmaxf(v3, 0.f);
            }
            if (outHalf) {
                __half* Ch = (__half*)Cout;
                *(__half2*)(Ch + (size_t)row * N + col)       = __floats2half2_rn(v0, v1);
                *(__half2*)(Ch + (size_t)(row + 8) * N + col) = __floats2half2_rn(v2, v3);
            } else {
                float* Cf = (float*)Cout;
                *(float2*)(Cf + (size_t)row * N + col)       = make_float2(v0, v1);
                *(float2*)(Cf + (size_t)(row + 8) * N + col) = make_float2(v2, v3);
            }
        }
    }
}

// ---------------- Fused GEMM + LayerNorm (BM=64, BN=256, K=256, ldmatrix) ----------------
// residual=0: OutH = fp16( LN(A @ WT^T) )        (merge + LN1)
// residual=1: F0 += LN(A @ WT^T); F0h = fp16(F0) (FFN2 + LN2 + residual)
#define LNA_WORDS (64 * RSW)
#define LNB_WORDS (256 * RSW)

__global__ __launch_bounds__(256, 2) void hgemm_ln_kernel(
    const __half* __restrict__ A, const __half* __restrict__ B,
    __half* __restrict__ OutH,
    float* __restrict__ F0, __half* __restrict__ F0h,
    const float* __restrict__ gam, const float* __restrict__ bet,
    int residual)
{
    __shared__ uint32_t As2[2][LNA_WORDS];
    __shared__ uint32_t Bs2[2][LNB_WORDS];
    __shared__ float sg[256], sb[256];
    __shared__ float srs[64], ssq[64];

    int tid = threadIdx.x;
    int warp = tid >> 5;
    int lane = tid & 31;
    int g = lane >> 2;
    int q = lane & 3;
    int rowBase = blockIdx.x * 64;
    int wm0 = (warp >> 2) * 32;     // 2 warps in M
    int wn0 = (warp & 3) * 64;      // 4 warps in N
    const int NS = 16;              // K = 256

    sg[tid] = gam[tid];
    sb[tid] = bet[tid];
    if (tid < 64) { srs[tid] = 0.0f; ssq[tid] = 0.0f; }

    float acc[2][8][4];
#pragma unroll
    for (int mt = 0; mt < 2; mt++)
#pragma unroll
        for (int nt = 0; nt < 8; nt++)
#pragma unroll
            for (int r = 0; r < 4; r++) acc[mt][nt][r] = 0.0f;

    // A: 128 chunks (tid<128): row = tid>>1, j = tid&1
    int aRow = tid >> 1, aJ = tid & 1;
    // B: 512 chunks: c = tid, tid+256: row = c>>1, j = c&1
    int bRow0 = tid >> 1,         bJ0 = tid & 1;
    int bRow1 = (tid + 256) >> 1, bJ1 = tid & 1;

    auto issue = [&](int s, int buf) {
        int k0 = s << 4;
        if (tid < 128)
            cp16(&As2[buf][aRow * RSW + aJ * 4],
                 A + (size_t)(rowBase + aRow) * 256 + k0 + aJ * 8);
        cp16(&Bs2[buf][bRow0 * RSW + bJ0 * 4], B + (size_t)bRow0 * 256 + k0 + bJ0 * 8);
        cp16(&Bs2[buf][bRow1 * RSW + bJ1 * 4], B + (size_t)bRow1 * 256 + k0 + bJ1 * 8);
    };

    int aOffW = (wm0 + (lane & 15)) * RSW + (lane >> 4) * 4;
    int bOffW = (wn0 + (lane & 7) + ((lane >> 4) << 3)) * RSW + ((lane >> 3) & 1) * 4;

    issue(0, 0);
    asm volatile("cp.async.commit_group;\n");

    int buf = 0;
    for (int s = 0; s < NS; s++) {
        if (s + 1 < NS) {
            issue(s + 1, buf ^ 1);
            asm volatile("cp.async.commit_group;\n");
            asm volatile("cp.async.wait_group 1;\n");
        } else {
            asm volatile("cp.async.wait_group 0;\n");
        }
        __syncthreads();

        uint32_t asBase = (uint32_t)__cvta_generic_to_shared(&As2[buf][0]);
        uint32_t bsBase = (uint32_t)__cvta_generic_to_shared(&Bs2[buf][0]);

        uint32_t af[2][4];
        ldsm4(af[0][0], af[0][1], af[0][2], af[0][3], asBase + aOffW * 4);
        ldsm4(af[1][0], af[1][1], af[1][2], af[1][3], asBase + (aOffW + 16 * RSW) * 4);
        uint32_t bf[8][2];
#pragma unroll
        for (int i = 0; i < 4; i++)
            ldsm4(bf[2*i][0], bf[2*i][1], bf[2*i+1][0], bf[2*i+1][1],
                  bsBase + (bOffW + i * 16 * RSW) * 4);

#pragma unroll
        for (int mt = 0; mt < 2; mt++)
#pragma unroll
            for (int nt = 0; nt < 8; nt++) {
                asm volatile(
                    "mma.sync.aligned.m16n8k16.row.col.f32.f16.f16.f32 "
                    "{%0,%1,%2,%3}, {%4,%5,%6,%7}, {%8,%9}, {%0,%1,%2,%3};\n"
                    : "+f"(acc[mt][nt][0]), "+f"(acc[mt][nt][1]),
                      "+f"(acc[mt][nt][2]), "+f"(acc[mt][nt][3])
                    : "r"(af[mt][0]), "r"(af[mt][1]), "r"(af[mt][2]), "r"(af[mt][3]),
                      "r"(bf[nt][0]), "r"(bf[nt][1]));
            }
        buf ^= 1;
        __syncthreads();
    }

    // ---- LayerNorm epilogue ----
#pragma unroll
    for (int mt = 0; mt < 2; mt++) {
#pragma unroll
        for (int hr = 0; hr < 2; hr++) {
            int rl = wm0 + mt * 16 + hr * 8 + g;
            float s1 = 0.0f, s2 = 0.0f;
#pragma unroll
            for (int nt = 0; nt < 8; nt++) {
                float v0 = acc[mt][nt][hr * 2], v1 = acc[mt][nt][hr * 2 + 1];
                s1 += v0 + v1;
                s2 += v0 * v0 + v1 * v1;
            }
            s1 += __shfl_xor_sync(0xffffffffu, s1, 1);
            s1 += __shfl_xor_sync(0xffffffffu, s1, 2);
            s2 += __shfl_xor_sync(0xffffffffu, s2, 1);
            s2 += __shfl_xor_sync(0xffffffffu, s2, 2);
            if (q == 0) {
                atomicAdd(&srs[rl], s1);
                atomicAdd(&ssq[rl], s2);
            }
        }
    }
    __syncthreads();

#pragma unroll
    for (int mt = 0; mt < 2; mt++) {
#pragma unroll
        for (int hr = 0; hr < 2; hr++) {
            int rl = wm0 + mt * 16 + hr * 8 + g;
            int row = rowBase + rl;
            float mu = srs[rl] * (1.0f / 256.0f);
            float var = ssq[rl] * (1.0f / 256.0f) - mu * mu;
            float rstd = rsqrtf(var + 1e-5f);
#pragma unroll
            for (int nt = 0; nt < 8; nt++) {
                int col = wn0 + nt * 8 + 2 * q;
                float v0 = (acc[mt][nt][hr * 2]     - mu) * rstd * sg[col]     + sb[col];
                float v1 = (acc[mt][nt][hr * 2 + 1] - mu) * rstd * sg[col + 1] + sb[col + 1];
                size_t o = (size_t)row * 256 + col;
                if (residual) {
                    float2 f = *(float2*)(F0 + o);
                    f.x += v0; f.y += v1;
                    *(float2*)(F0 + o) = f;
                    *(__half2*)(F0h + o) = __floats2half2_rn(f.x, f.y);
                } else {
                    *(__half2*)(OutH + o) = __floats2half2_rn(v0, v1);
                }
            }
        }
    }
}

// ---------------- KV = sum_s K[s,d]*v[s,e], Ksum per (n,h), fp16 inputs ----------------
#define KV_CHUNKS 20
#define KV_SC (LL / KV_CHUNKS)
__global__ void kv_reduce_kernel(const __half* __restrict__ Kb, const __half* __restrict__ Vb,
                                 float* __restrict__ KV, float* __restrict__ KS) {
    int nh = blockIdx.x;
    int n = nh >> 3, h = nh & 7;
    int t = threadIdx.x;
    int d = t & 31;
    int eg = t >> 5;
    int s0 = blockIdx.y * KV_SC;
    float a0 = 0, a1 = 0, a2 = 0, a3 = 0, ks = 0;
    for (int s = s0; s < s0 + KV_SC; s++) {
        size_t base = ((size_t)(n * LL + s) * NHD + h) * HDD;
        float kd = __half2float(Kb[base + d]);
        const __half2* vp = (const __half2*)(Vb + base + eg * 4);
        float2 f0 = __half22float2(vp[0]);
        float2 f1 = __half22float2(vp[1]);
        a0 = fmaf(kd, f0.x, a0);
        a1 = fmaf(kd, f0.y, a1);
        a2 = fmaf(kd, f1.x, a2);
        a3 = fmaf(kd, f1.y, a3);
        ks += kd;
    }
    float* kvp = KV + ((size_t)nh * HDD + d) * HDD + eg * 4;
    atomicAdd(kvp + 0, a0);
    atomicAdd(kvp + 1, a1);
    atomicAdd(kvp + 2, a2);
    atomicAdd(kvp + 3, a3);
    if (eg == 0) atomicAdd(KS + nh * HDD + d, ks);
}

// ---------------- out = (Q.KV[:,e]) / (Q.Ksum + eps); fp16 in/out (in-place) ----------------
#define AT_CHUNKS 40
#define AT_RPB (LL / AT_CHUNKS)
__global__ void attn_apply_kernel(__half* __restrict__ Qb, const float* __restrict__ KV,
                                  const float* __restrict__ KS) {
    __shared__ float kvs[32][33];
    __shared__ float kss[32];
    int n = blockIdx.z, h = blockIdx.y;
    int nh = n * NHD + h;
    int t = threadIdx.x, lane = t & 31, w = t >> 5;
    for (int i = t; i < 1024; i += 256) kvs[i >> 5][i & 31] = KV[(size_t)nh * 1024 + i];
    if (t < 32) kss[t] = KS[nh * 32 + t];
    __syncthreads();
    int l0 = blockIdx.x * AT_RPB + w * (AT_RPB / 8);
    for (int r = 0; r < AT_RPB / 8; r++) {
        int l = l0 + r;
        size_t base = ((size_t)(n * LL + l) * NHD + h) * HDD;
        float qd = __half2float(Qb[base + lane]);
        float zs = qd * kss[lane];
#pragma unroll
        for (int o = 16; o; o >>= 1) zs += __shfl_xor_sync(0xffffffffu, zs, o);
        float z = 1.0f / (zs + 1e-6f);
        float acc = 0.0f;
#pragma unroll
        for (int d = 0; d < 32; d++) {
            float qv = __shfl_sync(0xffffffffu, qd, d);
            acc = fmaf(qv, kvs[d][lane], acc);
        }
        Qb[base + lane] = __float2half_rn(acc * z);
    }
}

// ---------------- launch ----------------
extern "C" void kernel_launch(void* const* d_in, const int* in_sizes, int n_in,
                              void* d_out, int out_size) {
    const float* feat0 = (const float*)d_in[0];
    const float* feat1 = (const float*)d_in[1];
    const float* Wq = (const float*)d_in[2];
    const float* Wk = (const float*)d_in[3];
    const float* Wv = (const float*)d_in[4];
    const float* Wm = (const float*)d_in[5];
    const float* W1 = (const float*)d_in[6];
    const float* W2 = (const float*)d_in[7];
    const float* g1 = (const float*)d_in[8];
    const float* b1 = (const float*)d_in[9];
    const float* g2 = (const float*)d_in[10];
    const float* b2 = (const float*)d_in[11];

    float *F0, *KV, *KS, *PE;
    __half *F0h, *F1h, *Qh, *Kh, *Vh;
    __half *wQ, *wK, *wV, *wM, *w1p, *w2p;
    cudaGetSymbolAddress((void**)&F0,  g_F0);
    cudaGetSymbolAddress((void**)&KV,  g_KV);
    cudaGetSymbolAddress((void**)&KS,  g_KS);
    cudaGetSymbolAddress((void**)&PE,  g_PE);
    cudaGetSymbolAddress((void**)&F0h, g_F0h);
    cudaGetSymbolAddress((void**)&F1h, g_F1h);
    cudaGetSymbolAddress((void**)&Qh,  g_Qh);
    cudaGetSymbolAddress((void**)&Kh,  g_Kh);
    cudaGetSymbolAddress((void**)&Vh,  g_Vh);
    cudaGetSymbolAddress((void**)&wQ,  g_WqH);
    cudaGetSymbolAddress((void**)&wK,  g_WkH);
    cudaGetSymbolAddress((void**)&wV,  g_WvH);
    cudaGetSymbolAddress((void**)&wM,  g_WmH);
    cudaGetSymbolAddress((void**)&w1p, g_W1H);
    cudaGetSymbolAddress((void**)&w2p, g_W2H);

    weight_prep_kernel<<<(2 * 2 * CD * CD + 255) / 256, 256>>>(Wq, Wk, Wv, Wm, W1, W2);
    pe_precompute_kernel<<<(CD * LL + 255) / 256, 256>>>(PE);

    dim3 tb(32, 8);
    dim3 tg(LL / 32, CD / 32, NB);
    build_pe_kernel<<<tg, tb>>>(feat0, PE, F0, F0h);
    build_pe_kernel<<<tg, tb>>>(feat1, PE, nullptr, F1h);

    dim3 gg(CD / 128, MR / 128);
    const int GLN = MR / 64;   // 1200 CTAs for fused LN GEMMs

    for (int i = 0; i < 2; i++) {
        const __half* wq = wQ + (size_t)i * CD * CD;
        const __half* wk = wK + (size_t)i * CD * CD;
        const __half* wv = wV + (size_t)i * CD * CD;
        const __half* wm = wM + (size_t)i * CD * CD;
        const __half* w1 = w1p + (size_t)i * 2 * CD * CD;
        const __half* w2 = w2p + (size_t)i * CD * CD;

        // projections (fp16 out): q -> Qh, k -> Kh, v -> Vh
        hgemm_kernel<<<gg, 256>>>(F0h, F0h, wq, Qh, MR, CD, CD, CD, EPI_ELU1, 1);
        hgemm_kernel<<<gg, 256>>>(F1h, F1h, wk, Kh, MR, CD, CD, CD, EPI_ELU1, 1);
        hgemm_kernel<<<gg, 256>>>(F1h, F1h, wv, Vh, MR, CD, CD, CD, EPI_NONE, 1);

        cudaMemsetAsync(KV, 0, sizeof(float) * NB * NHD * HDD * HDD, 0);
        cudaMemsetAsync(KS, 0, sizeof(float) * NB * NHD * HDD, 0);
        kv_reduce_kernel<<<dim3(NB * NHD, KV_CHUNKS), 256>>>(Kh, Vh, KV, KS);

        // attention apply in place on Qh
        attn_apply_kernel<<<dim3(AT_CHUNKS, NHD, NB), 256>>>(Qh, KV, KS);

        // merge + LN1 fused: Vh = fp16( LN(Qh @ Wm) )
        hgemm_ln_kernel<<<GLN, 256>>>(Qh, wm, Vh, nullptr, nullptr,
                                      g1 + i * CD, b1 + i * CD, 0);

        // FFN1: relu([F0h|Vh] @ W1) -> Kh (fp16)
        hgemm_kernel<<<gg, 256>>>(F0h, Vh, w1, Kh, MR, 2 * CD, CD, CD, EPI_RELU, 1);

        // FFN2 + LN2 + residual fused: F0 += LN(Kh @ W2); F0h = fp16(F0)
        hgemm_ln_kernel<<<GLN, 256>>>(Kh, w2, nullptr, F0, F0h,
                                      g2 + i * CD, b2 + i * CD, 1);
    }

    unbuild_kernel<<<tg, tb>>>(F0, (float*)d_out);
}

// round 13
// speedup vs baseline: 1.1166x; 1.1166x over previous
#include <cuda_runtime.h>
#include <cuda_fp16.h>
#include <cstdint>

// Problem constants
#define NB    16
#define CD    256
#define HH    80
#define WW    60
#define LL    4800            // HH*WW
#define NHD   8
#define HDD   32
#define MR    (NB*LL)         // 76800 rows

#define EPI_NONE 0
#define EPI_ELU1 1
#define EPI_RELU 2
#define EPI_QKV  3            // ELU1 for cols < 512, NONE for cols >= 512

// ---------------- scratch (static device globals; no allocation) ----------------
__device__ float  g_F0  [(size_t)MR * CD];     // exact x (residual/output)
__device__ __half g_F0h [(size_t)MR * CD];
__device__ __half g_F1h [(size_t)MR * CD];
__device__ __half g_QKVh[(size_t)MR * 3 * CD]; // [MR][768]: Q|K|V
__device__ __half g_Mh  [(size_t)MR * CD];     // merge+LN1 output
__device__ __half g_Hh  [(size_t)MR * CD];     // FFN1 output
__device__ float  g_PE  [(size_t)CD * LL];
__device__ float  g_KVS [NB * NHD * (HDD * HDD + HDD)];  // KV then KS
#define KVS_KV_SZ (NB * NHD * HDD * HDD)
// fp16 weights, k-pair interleaved: WH[((k>>1)*N + n)*2 + (k&1)] = W[k][n]
__device__ __half g_Wqkv[2 * CD * 3 * CD];     // [128][768][2] per layer
__device__ __half g_WmH [2 * CD * CD];
__device__ __half g_W1H [2 * 2 * CD * CD];
__device__ __half g_W2H [2 * CD * CD];

// ---------------- weight prep: fp16 + k-pair interleave ----------------
__global__ void weight_prep_kernel(
    const float* __restrict__ wq, const float* __restrict__ wk,
    const float* __restrict__ wv, const float* __restrict__ wm,
    const float* __restrict__ w1, const float* __restrict__ w2)
{
    int i = blockIdx.x * blockDim.x + threadIdx.x;
    const int S = 2 * CD * CD;              // 131072
    if (i < S) {
        int li = i >> 16;                   // CD*CD = 65536
        int r  = i & 65535;
        int k = r >> 8, n = r & 255;
        int kp = ((k >> 1) * 768) * 2 + (k & 1);
        int base = li * 196608;
        g_Wqkv[base + kp + (n      ) * 2] = __float2half_rn(wq[i]);
        g_Wqkv[base + kp + (n + 256) * 2] = __float2half_rn(wk[i]);
        g_Wqkv[base + kp + (n + 512) * 2] = __float2half_rn(wv[i]);
        int dst = li * 65536 + (((k >> 1) << 8) + n) * 2 + (k & 1);
        g_WmH[dst] = __float2half_rn(wm[i]);
        g_W2H[dst] = __float2half_rn(w2[i]);
    }
    if (i < 2 * S) {                        // W1: [512][256] per layer
        int li = i >> 17;
        int r  = i & 131071;
        int k = r >> 8, n = r & 255;
        int dst = li * 131072 + (((k >> 1) << 8) + n) * 2 + (k & 1);
        g_W1H[dst] = __float2half_rn(w1[i]);
    }
}

// ---------------- positional encoding ----------------
// fac = (-log(1e4)/256)//2 == -1.0  =>  div[j] = exp(-2*j)
__global__ void pe_precompute_kernel(float* __restrict__ PE) {
    int idx = blockIdx.x * blockDim.x + threadIdx.x;
    if (idx >= CD * LL) return;
    int c = idx / LL, l = idx % LL;
    int j = c >> 2, r = c & 3;
    int h = l / WW, w = l % WW;
    float f = expf(-2.0f * (float)j);
    float pos = (r < 2) ? (float)(w + 1) : (float)(h + 1);
    float arg = pos * f;
    PE[idx] = (r & 1) ? cosf(arg) : sinf(arg);
}

// NCHW -> [N,L,C] with PE; writes optional f32 + fp16
__global__ void build_pe_kernel(const float* __restrict__ feat, const float* __restrict__ PE,
                                float* __restrict__ outF, __half* __restrict__ outH) {
    __shared__ float tile[32][33];
    int n  = blockIdx.z;
    int c0 = blockIdx.y * 32;
    int l0 = blockIdx.x * 32;
    int tx = threadIdx.x, ty = threadIdx.y;
#pragma unroll
    for (int i = 0; i < 4; i++) {
        int c = c0 + ty + i * 8;
        int l = l0 + tx;
        tile[ty + i * 8][tx] = feat[((size_t)n * CD + c) * LL + l] + PE[(size_t)c * LL + l];
    }
    __syncthreads();
#pragma unroll
    for (int i = 0; i < 4; i++) {
        int l = l0 + ty + i * 8;
        int c = c0 + tx;
        float v = tile[tx][ty + i * 8];
        size_t o = ((size_t)n * LL + l) * CD + c;
        if (outF) outF[o] = v;
        outH[o] = __float2half_rn(v);
    }
}

__global__ void unbuild_kernel(const float* __restrict__ in, float* __restrict__ out) {
    __shared__ float tile[32][33];
    int n  = blockIdx.z;
    int c0 = blockIdx.y * 32;
    int l0 = blockIdx.x * 32;
    int tx = threadIdx.x, ty = threadIdx.y;
#pragma unroll
    for (int i = 0; i < 4; i++) {
        int l = l0 + ty + i * 8;
        int c = c0 + tx;
        tile[ty + i * 8][tx] = in[((size_t)n * LL + l) * CD + c];
    }
    __syncthreads();
#pragma unroll
    for (int i = 0; i < 4; i++) {
        int c = c0 + ty + i * 8;
        int l = l0 + tx;
        out[((size_t)n * CD + c) * LL + l] = tile[tx][ty + i * 8];
    }
}

// ---------------- FP16 tensor-core GEMM (m16n8k16, f32 accum) ----------------
// C[M,N] = epi( A' @ B ), B fp16 k-pair interleaved ([K/2][N] 32-bit words).
// qkvMode=0: A' = [A|A2] concat over K (row strides K1, K2 halves).
// qkvMode=1: A' = (colBase < 256 ? A : A2), Ktot=K1, both stride K1.
// BM=BN=128, BK=16, 8 warps, warp tile 32x64. Double-buffered cp.async.
#define ASW 12                 // A row stride in 32-bit words (16 halves + pad)
#define BSW 136                // B k-pair row stride in words (128 + pad)
#define AS_WORDS (128 * ASW)
#define BS_WORDS (8 * BSW)

__device__ __forceinline__ void cp16(void* dst, const void* src) {
    uint32_t d = (uint32_t)__cvta_generic_to_shared(dst);
    asm volatile("cp.async.cg.shared.global [%0], [%1], 16;\n" :: "r"(d), "l"(src));
}

__global__ __launch_bounds__(256, 2) void hgemm_kernel(
    const __half* __restrict__ A, const __half* __restrict__ A2,
    const __half* __restrict__ B, void* __restrict__ Cout,
    int M, int Ktot, int K1, int N, int epi, int outHalf, int qkvMode)
{
    __shared__ uint32_t As2[2][AS_WORDS];
    __shared__ uint32_t Bs2[2][BS_WORDS];

    int tid = threadIdx.x;
    int warp = tid >> 5;
    int lane = tid & 31;
    int g = lane >> 2;
    int q = lane & 3;
    int rowBase = blockIdx.y * 128;
    int colBase = blockIdx.x * 128;
    int wm0 = (warp >> 1) * 32;
    int wn0 = (warp & 1) * 64;
    int K2 = Ktot - K1;
    int NS = Ktot >> 4;

    // resolve epilogue + A source for qkv mode
    int myEpi = epi;
    const __half* Abase = A;
    if (qkvMode) {
        myEpi = (colBase < 512) ? EPI_ELU1 : EPI_NONE;
        Abase = (colBase < 256) ? A : A2;
    }

    float acc[2][8][4];
#pragma unroll
    for (int mt = 0; mt < 2; mt++)
#pragma unroll
        for (int nt = 0; nt < 8; nt++)
#pragma unroll
            for (int r = 0; r < 4; r++) acc[mt][nt][r] = 0.0f;

    int aRow = tid >> 1, aJ = tid & 1;
    int bKp = tid >> 5, bN0 = (tid & 31) << 2;

    auto issue = [&](int s, int buf) {
        int k0 = s << 4;
        int kk = k0 + aJ * 8;
        const __half* srcA;
        if (qkvMode) {
            srcA = Abase + (size_t)(rowBase + aRow) * K1 + kk;
        } else {
            srcA = (kk < K1)
                ? (A  + (size_t)(rowBase + aRow) * K1 + kk)
                : (A2 + (size_t)(rowBase + aRow) * K2 + (kk - K1));
        }
        cp16(&As2[buf][aRow * ASW + aJ * 4], srcA);
        const uint32_t* Bw = (const uint32_t*)B;
        cp16(&Bs2[buf][bKp * BSW + bN0],
             Bw + (size_t)(s * 8 + bKp) * N + colBase + bN0);
    };

    issue(0, 0);
    asm volatile("cp.async.commit_group;\n");

    int buf = 0;
    for (int s = 0; s < NS; s++) {
        if (s + 1 < NS) {
            issue(s + 1, buf ^ 1);
            asm volatile("cp.async.commit_group;\n");
            asm volatile("cp.async.wait_group 1;\n");
        } else {
            asm volatile("cp.async.wait_group 0;\n");
        }
        __syncthreads();

        const uint32_t* AsB = As2[buf];
        const uint32_t* BsB = Bs2[buf];
        uint32_t af[2][4];
#pragma unroll
        for (int mt = 0; mt < 2; mt++) {
            int m = wm0 + mt * 16;
            af[mt][0] = AsB[(m + g    ) * ASW + q    ];
            af[mt][1] = AsB[(m + g + 8) * ASW + q    ];
            af[mt][2] = AsB[(m + g    ) * ASW + q + 4];
            af[mt][3] = AsB[(m + g + 8) * ASW + q + 4];
        }
        uint32_t bf[8][2];
#pragma unroll
        for (int nt = 0; nt < 8; nt++) {
            int n = wn0 + nt * 8 + g;
            bf[nt][0] = BsB[q       * BSW + n];
            bf[nt][1] = BsB[(q + 4) * BSW + n];
        }
#pragma unroll
        for (int mt = 0; mt < 2; mt++)
#pragma unroll
            for (int nt = 0; nt < 8; nt++) {
                asm volatile(
                    "mma.sync.aligned.m16n8k16.row.col.f32.f16.f16.f32 "
                    "{%0,%1,%2,%3}, {%4,%5,%6,%7}, {%8,%9}, {%0,%1,%2,%3};\n"
                    : "+f"(acc[mt][nt][0]), "+f"(acc[mt][nt][1]),
                      "+f"(acc[mt][nt][2]), "+f"(acc[mt][nt][3])
                    : "r"(af[mt][0]), "r"(af[mt][1]), "r"(af[mt][2]), "r"(af[mt][3]),
                      "r"(bf[nt][0]), "r"(bf[nt][1]));
            }
        buf ^= 1;
        __syncthreads();
    }

#pragma unroll
    for (int mt = 0; mt < 2; mt++) {
        int row = rowBase + wm0 + mt * 16 + g;
#pragma unroll
        for (int nt = 0; nt < 8; nt++) {
            int col = colBase + wn0 + nt * 8 + 2 * q;
            float v0 = acc[mt][nt][0], v1 = acc[mt][nt][1];
            float v2 = acc[mt][nt][2], v3 = acc[mt][nt][3];
            if (myEpi == EPI_ELU1) {
                v0 = (v0 > 0.f) ? v0 + 1.f : expf(v0);
                v1 = (v1 > 0.f) ? v1 + 1.f : expf(v1);
                v2 = (v2 > 0.f) ? v2 + 1.f : expf(v2);
                v3 = (v3 > 0.f) ? v3 + 1.f : expf(v3);
            } else if (myEpi == EPI_RELU) {
                v0 = fmaxf(v0, 0.f); v1 = fmaxf(v1, 0.f);
                v2 = fmaxf(v2, 0.f); v3 = fmaxf(v3, 0.f);
            }
            if (outHalf) {
                __half* Ch = (__half*)Cout;
                *(__half2*)(Ch + (size_t)row * N + col)       = __floats2half2_rn(v0, v1);
                *(__half2*)(Ch + (size_t)(row + 8) * N + col) = __floats2half2_rn(v2, v3);
            } else {
                float* Cf = (float*)Cout;
                *(float2*)(Cf + (size_t)row * N + col)       = make_float2(v0, v1);
                *(float2*)(Cf + (size_t)(row + 8) * N + col) = make_float2(v2, v3);
            }
        }
    }
}

// ---------------- Fused GEMM + LayerNorm (BM=64, BN=256, K=256) ----------------
// residual=0: OutH = fp16( LN(A @ B) )          (merge + LN1); A row stride sA halves
// residual=1: F0 += LN(A @ B); F0h = fp16(F0)   (FFN2 + LN2 + residual)
#define LASW 12
#define LBSW 264

__global__ __launch_bounds__(256, 2) void hgemm_ln_kernel(
    const __half* __restrict__ A, int sA, const __half* __restrict__ B,
    __half* __restrict__ OutH,
    float* __restrict__ F0, __half* __restrict__ F0h,
    const float* __restrict__ gam, const float* __restrict__ bet,
    int residual)
{
    __shared__ uint32_t As2[2][64 * LASW];
    __shared__ uint32_t Bs2[2][8 * LBSW];
    __shared__ float sg[256], sb[256];
    __shared__ float srs[64], ssq[64];

    int tid = threadIdx.x;
    int warp = tid >> 5;
    int lane = tid & 31;
    int g = lane >> 2;
    int q = lane & 3;
    int rowBase = blockIdx.x * 64;
    int wm0 = (warp >> 2) * 32;     // 2 warps in M
    int wn0 = (warp & 3) * 64;      // 4 warps in N
    const int NS = 16;              // K = 256

    sg[tid] = gam[tid];
    sb[tid] = bet[tid];
    if (tid < 64) { srs[tid] = 0.0f; ssq[tid] = 0.0f; }

    float acc[2][8][4];
#pragma unroll
    for (int mt = 0; mt < 2; mt++)
#pragma unroll
        for (int nt = 0; nt < 8; nt++)
#pragma unroll
            for (int r = 0; r < 4; r++) acc[mt][nt][r] = 0.0f;

    int aRow = tid >> 1, aJ = tid & 1;
    int bR0 = tid >> 6,         bC0 = (tid & 63) << 2;
    int bR1 = (tid + 256) >> 6, bC1 = bC0;

    auto issue = [&](int s, int buf) {
        int k0 = s << 4;
        if (tid < 128)
            cp16(&As2[buf][aRow * LASW + aJ * 4],
                 A + (size_t)(rowBase + aRow) * sA + k0 + aJ * 8);
        const uint32_t* Bw = (const uint32_t*)B;
        cp16(&Bs2[buf][bR0 * LBSW + bC0], Bw + (size_t)(s * 8 + bR0) * 256 + bC0);
        cp16(&Bs2[buf][bR1 * LBSW + bC1], Bw + (size_t)(s * 8 + bR1) * 256 + bC1);
    };

    issue(0, 0);
    asm volatile("cp.async.commit_group;\n");

    int buf = 0;
    for (int s = 0; s < NS; s++) {
        if (s + 1 < NS) {
            issue(s + 1, buf ^ 1);
            asm volatile("cp.async.commit_group;\n");
            asm volatile("cp.async.wait_group 1;\n");
        } else {
            asm volatile("cp.async.wait_group 0;\n");
        }
        __syncthreads();

        const uint32_t* AsB = As2[buf];
        const uint32_t* BsB = Bs2[buf];
        uint32_t af[2][4];
#pragma unroll
        for (int mt = 0; mt < 2; mt++) {
            int m = wm0 + mt * 16;
            af[mt][0] = AsB[(m + g    ) * LASW + q    ];
            af[mt][1] = AsB[(m + g + 8) * LASW + q    ];
            af[mt][2] = AsB[(m + g    ) * LASW + q + 4];
            af[mt][3] = AsB[(m + g + 8) * LASW + q + 4];
        }
        uint32_t bf[8][2];
#pragma unroll
        for (int nt = 0; nt < 8; nt++) {
            int n = wn0 + nt * 8 + g;
            bf[nt][0] = BsB[q       * LBSW + n];
            bf[nt][1] = BsB[(q + 4) * LBSW + n];
        }
#pragma unroll
        for (int mt = 0; mt < 2; mt++)
#pragma unroll
            for (int nt = 0; nt < 8; nt++) {
                asm volatile(
                    "mma.sync.aligned.m16n8k16.row.col.f32.f16.f16.f32 "
                    "{%0,%1,%2,%3}, {%4,%5,%6,%7}, {%8,%9}, {%0,%1,%2,%3};\n"
                    : "+f"(acc[mt][nt][0]), "+f"(acc[mt][nt][1]),
                      "+f"(acc[mt][nt][2]), "+f"(acc[mt][nt][3])
                    : "r"(af[mt][0]), "r"(af[mt][1]), "r"(af[mt][2]), "r"(af[mt][3]),
                      "r"(bf[nt][0]), "r"(bf[nt][1]));
            }
        buf ^= 1;
        __syncthreads();
    }

    // ---- LayerNorm epilogue ----
#pragma unroll
    for (int mt = 0; mt < 2; mt++) {
#pragma unroll
        for (int hr = 0; hr < 2; hr++) {
            int rl = wm0 + mt * 16 + hr * 8 + g;
            float s1 = 0.0f, s2 = 0.0f;
#pragma unroll
            for (int nt = 0; nt < 8; nt++) {
                float v0 = acc[mt][nt][hr * 2], v1 = acc[mt][nt][hr * 2 + 1];
                s1 += v0 + v1;
                s2 += v0 * v0 + v1 * v1;
            }
            s1 += __shfl_xor_sync(0xffffffffu, s1, 1);
            s1 += __shfl_xor_sync(0xffffffffu, s1, 2);
            s2 += __shfl_xor_sync(0xffffffffu, s2, 1);
            s2 += __shfl_xor_sync(0xffffffffu, s2, 2);
            if (q == 0) {
                atomicAdd(&srs[rl], s1);
                atomicAdd(&ssq[rl], s2);
            }
        }
    }
    __syncthreads();

#pragma unroll
    for (int mt = 0; mt < 2; mt++) {
#pragma unroll
        for (int hr = 0; hr < 2; hr++) {
            int rl = wm0 + mt * 16 + hr * 8 + g;
            int row = rowBase + rl;
            float mu = srs[rl] * (1.0f / 256.0f);
            float var = ssq[rl] * (1.0f / 256.0f) - mu * mu;
            float rstd = rsqrtf(var + 1e-5f);
#pragma unroll
            for (int nt = 0; nt < 8; nt++) {
                int col = wn0 + nt * 8 + 2 * q;
                float v0 = (acc[mt][nt][hr * 2]     - mu) * rstd * sg[col]     + sb[col];
                float v1 = (acc[mt][nt][hr * 2 + 1] - mu) * rstd * sg[col + 1] + sb[col + 1];
                size_t o = (size_t)row * 256 + col;
                if (residual) {
                    float2 f = *(float2*)(F0 + o);
                    f.x += v0; f.y += v1;
                    *(float2*)(F0 + o) = f;
                    *(__half2*)(F0h + o) = __floats2half2_rn(f.x, f.y);
                } else {
                    *(__half2*)(OutH + o) = __floats2half2_rn(v0, v1);
                }
            }
        }
    }
}

// ---------------- KV = sum_s K[s,d]*v[s,e], Ksum per (n,h); QKV layout stride 768 ----------------
#define KV_CHUNKS 20
#define KV_SC (LL / KV_CHUNKS)
__global__ void kv_reduce_kernel(const __half* __restrict__ QKV,
                                 float* __restrict__ KV, float* __restrict__ KS) {
    int nh = blockIdx.x;
    int n = nh >> 3, h = nh & 7;
    int t = threadIdx.x;
    int d = t & 31;
    int eg = t >> 5;
    int s0 = blockIdx.y * KV_SC;
    float a0 = 0, a1 = 0, a2 = 0, a3 = 0, ks = 0;
    for (int s = s0; s < s0 + KV_SC; s++) {
        size_t rowb = (size_t)(n * LL + s) * 768 + h * HDD;
        float kd = __half2float(QKV[rowb + 256 + d]);
        const __half2* vp = (const __half2*)(QKV + rowb + 512 + eg * 4);
        float2 f0 = __half22float2(vp[0]);
        float2 f1 = __half22float2(vp[1]);
        a0 = fmaf(kd, f0.x, a0);
        a1 = fmaf(kd, f0.y, a1);
        a2 = fmaf(kd, f1.x, a2);
        a3 = fmaf(kd, f1.y, a3);
        ks += kd;
    }
    float* kvp = KV + ((size_t)nh * HDD + d) * HDD + eg * 4;
    atomicAdd(kvp + 0, a0);
    atomicAdd(kvp + 1, a1);
    atomicAdd(kvp + 2, a2);
    atomicAdd(kvp + 3, a3);
    if (eg == 0) atomicAdd(KS + nh * HDD + d, ks);
}

// ---------------- attn: Q region of QKV (stride 768) updated in place ----------------
#define AT_CHUNKS 40
#define AT_RPB (LL / AT_CHUNKS)
__global__ void attn_apply_kernel(__half* __restrict__ QKV, const float* __restrict__ KV,
                                  const float* __restrict__ KS) {
    __shared__ float kvs[32][33];
    __shared__ float kss[32];
    int n = blockIdx.z, h = blockIdx.y;
    int nh = n * NHD + h;
    int t = threadIdx.x, lane = t & 31, w = t >> 5;
    for (int i = t; i < 1024; i += 256) kvs[i >> 5][i & 31] = KV[(size_t)nh * 1024 + i];
    if (t < 32) kss[t] = KS[nh * 32 + t];
    __syncthreads();
    int l0 = blockIdx.x * AT_RPB + w * (AT_RPB / 8);
    for (int r = 0; r < AT_RPB / 8; r++) {
        int l = l0 + r;
        size_t base = (size_t)(n * LL + l) * 768 + h * HDD;
        float qd = __half2float(QKV[base + lane]);
        float zs = qd * kss[lane];
#pragma unroll
        for (int o = 16; o; o >>= 1) zs += __shfl_xor_sync(0xffffffffu, zs, o);
        float z = 1.0f / (zs + 1e-6f);
        float acc = 0.0f;
#pragma unroll
        for (int d = 0; d < 32; d++) {
            float qv = __shfl_sync(0xffffffffu, qd, d);
            acc = fmaf(qv, kvs[d][lane], acc);
        }
        QKV[base + lane] = __float2half_rn(acc * z);
    }
}

// ---------------- launch ----------------
extern "C" void kernel_launch(void* const* d_in, const int* in_sizes, int n_in,
                              void* d_out, int out_size) {
    const float* feat0 = (const float*)d_in[0];
    const float* feat1 = (const float*)d_in[1];
    const float* Wq = (const float*)d_in[2];
    const float* Wk = (const float*)d_in[3];
    const float* Wv = (const float*)d_in[4];
    const float* Wm = (const float*)d_in[5];
    const float* W1 = (const float*)d_in[6];
    const float* W2 = (const float*)d_in[7];
    const float* g1 = (const float*)d_in[8];
    const float* b1 = (const float*)d_in[9];
    const float* g2 = (const float*)d_in[10];
    const float* b2 = (const float*)d_in[11];

    float *F0, *KVS, *PE;
    __half *F0h, *F1h, *QKVh, *Mh, *Hh;
    __half *wQKV, *wM, *w1p, *w2p;
    cudaGetSymbolAddress((void**)&F0,   g_F0);
    cudaGetSymbolAddress((void**)&KVS,  g_KVS);
    cudaGetSymbolAddress((void**)&PE,   g_PE);
    cudaGetSymbolAddress((void**)&F0h,  g_F0h);
    cudaGetSymbolAddress((void**)&F1h,  g_F1h);
    cudaGetSymbolAddress((void**)&QKVh, g_QKVh);
    cudaGetSymbolAddress((void**)&Mh,   g_Mh);
    cudaGetSymbolAddress((void**)&Hh,   g_Hh);
    cudaGetSymbolAddress((void**)&wQKV, g_Wqkv);
    cudaGetSymbolAddress((void**)&wM,   g_WmH);
    cudaGetSymbolAddress((void**)&w1p,  g_W1H);
    cudaGetSymbolAddress((void**)&w2p,  g_W2H);
    float* KV = KVS;
    float* KS = KVS + KVS_KV_SZ;

    weight_prep_kernel<<<(2 * 2 * CD * CD + 255) / 256, 256>>>(Wq, Wk, Wv, Wm, W1, W2);
    pe_precompute_kernel<<<(CD * LL + 255) / 256, 256>>>(PE);

    dim3 tb(32, 8);
    dim3 tg(LL / 32, CD / 32, NB);
    build_pe_kernel<<<tg, tb>>>(feat0, PE, F0, F0h);
    build_pe_kernel<<<tg, tb>>>(feat1, PE, nullptr, F1h);

    dim3 ggQKV(6, MR / 128);   // N=768
    dim3 gg(CD / 128, MR / 128);
    const int GLN = MR / 64;

    for (int i = 0; i < 2; i++) {
        const __half* wqkv = wQKV + (size_t)i * CD * 3 * CD;
        const __half* wm = wM + (size_t)i * CD * CD;
        const __half* w1 = w1p + (size_t)i * 2 * CD * CD;
        const __half* w2 = w2p + (size_t)i * CD * CD;

        // fused Q|K|V projection: QKVh[MR][768]
        hgemm_kernel<<<ggQKV, 256>>>(F0h, F1h, wqkv, QKVh,
                                     MR, CD, CD, 3 * CD, EPI_QKV, 1, 1);

        cudaMemsetAsync(KVS, 0, sizeof(float) * NB * NHD * (HDD * HDD + HDD), 0);
        kv_reduce_kernel<<<dim3(NB * NHD, KV_CHUNKS), 256>>>(QKVh, KV, KS);

        // attention apply in place on Q region
        attn_apply_kernel<<<dim3(AT_CHUNKS, NHD, NB), 256>>>(QKVh, KV, KS);

        // merge + LN1 fused: Mh = fp16( LN(Q @ Wm) )   (A stride 768)
        hgemm_ln_kernel<<<GLN, 256>>>(QKVh, 768, wm, Mh, nullptr, nullptr,
                                      g1 + i * CD, b1 + i * CD, 0);

        // FFN1: relu([F0h|Mh] @ W1) -> Hh (fp16)
        hgemm_kernel<<<gg, 256>>>(F0h, Mh, w1, Hh, MR, 2 * CD, CD, CD, EPI_RELU, 1, 0);

        // FFN2 + LN2 + residual fused: F0 += LN(Hh @ W2); F0h = fp16(F0)
        hgemm_ln_kernel<<<GLN, 256>>>(Hh, 256, w2, nullptr, F0, F0h,
                                      g2 + i * CD, b2 + i * CD, 1);
    }

    unbuild_kernel<<<tg, tb>>>(F0, (float*)d_out);
}

// round 16
// speedup vs baseline: 1.1540x; 1.0335x over previous
#include <cuda_runtime.h>
#include <cuda_fp16.h>
#include <cstdint>

// Problem constants
#define NB    16
#define CD    256
#define HH    80
#define WW    60
#define LL    4800            // HH*WW
#define NHD   8
#define HDD   32
#define MR    (NB*LL)         // 76800 rows

#define EPI_NONE 0
#define EPI_ELU1 1
#define EPI_RELU 2
#define EPI_QKV  3            // ELU1 for cols < 512, NONE for cols >= 512

// ---------------- scratch (static device globals; no allocation) ----------------
__device__ float  g_F0  [(size_t)MR * CD];     // exact x (residual/output)
__device__ __half g_F0h [(size_t)MR * CD];
__device__ __half g_F1h [(size_t)MR * CD];
__device__ __half g_QKVh[(size_t)MR * 3 * CD]; // [MR][768]: Q|K|V
__device__ __half g_Mh  [(size_t)MR * CD];     // merge+LN1 output
__device__ __half g_Hh  [(size_t)MR * CD];     // FFN1 output
__device__ float  g_PE  [(size_t)CD * LL];
__device__ float  g_KVS [NB * NHD * (HDD * HDD + HDD)];  // KV then KS
#define KVS_KV_SZ (NB * NHD * HDD * HDD)
// fp16 weights, k-pair interleaved: WH[((k>>1)*N + n)*2 + (k&1)] = W[k][n]
__device__ __half g_Wqkv[2 * CD * 3 * CD];     // [128][768][2] per layer
__device__ __half g_WmH [2 * CD * CD];
__device__ __half g_W1H [2 * 2 * CD * CD];
__device__ __half g_W2H [2 * CD * CD];

// ---------------- weight prep: fp16 + k-pair interleave ----------------
__global__ void weight_prep_kernel(
    const float* __restrict__ wq, const float* __restrict__ wk,
    const float* __restrict__ wv, const float* __restrict__ wm,
    const float* __restrict__ w1, const float* __restrict__ w2)
{
    int i = blockIdx.x * blockDim.x + threadIdx.x;
    const int S = 2 * CD * CD;              // 131072
    if (i < S) {
        int li = i >> 16;                   // CD*CD = 65536
        int r  = i & 65535;
        int k = r >> 8, n = r & 255;
        int kp = ((k >> 1) * 768) * 2 + (k & 1);
        int base = li * 196608;
        g_Wqkv[base + kp + (n      ) * 2] = __float2half_rn(wq[i]);
        g_Wqkv[base + kp + (n + 256) * 2] = __float2half_rn(wk[i]);
        g_Wqkv[base + kp + (n + 512) * 2] = __float2half_rn(wv[i]);
        int dst = li * 65536 + (((k >> 1) << 8) + n) * 2 + (k & 1);
        g_WmH[dst] = __float2half_rn(wm[i]);
        g_W2H[dst] = __float2half_rn(w2[i]);
    }
    if (i < 2 * S) {                        // W1: [512][256] per layer
        int li = i >> 17;
        int r  = i & 131071;
        int k = r >> 8, n = r & 255;
        int dst = li * 131072 + (((k >> 1) << 8) + n) * 2 + (k & 1);
        g_W1H[dst] = __float2half_rn(w1[i]);
    }
}

// ---------------- positional encoding ----------------
// fac = (-log(1e4)/256)//2 == -1.0  =>  div[j] = exp(-2*j)
__global__ void pe_precompute_kernel(float* __restrict__ PE) {
    int idx = blockIdx.x * blockDim.x + threadIdx.x;
    if (idx >= CD * LL) return;
    int c = idx / LL, l = idx % LL;
    int j = c >> 2, r = c & 3;
    int h = l / WW, w = l % WW;
    float f = expf(-2.0f * (float)j);
    float pos = (r < 2) ? (float)(w + 1) : (float)(h + 1);
    float arg = pos * f;
    PE[idx] = (r & 1) ? cosf(arg) : sinf(arg);
}

// NCHW -> [N,L,C] with PE; writes optional f32 + fp16
__global__ void build_pe_kernel(const float* __restrict__ feat, const float* __restrict__ PE,
                                float* __restrict__ outF, __half* __restrict__ outH) {
    __shared__ float tile[32][33];
    int n  = blockIdx.z;
    int c0 = blockIdx.y * 32;
    int l0 = blockIdx.x * 32;
    int tx = threadIdx.x, ty = threadIdx.y;
#pragma unroll
    for (int i = 0; i < 4; i++) {
        int c = c0 + ty + i * 8;
        int l = l0 + tx;
        tile[ty + i * 8][tx] = feat[((size_t)n * CD + c) * LL + l] + PE[(size_t)c * LL + l];
    }
    __syncthreads();
#pragma unroll
    for (int i = 0; i < 4; i++) {
        int l = l0 + ty + i * 8;
        int c = c0 + tx;
        float v = tile[tx][ty + i * 8];
        size_t o = ((size_t)n * LL + l) * CD + c;
        if (outF) outF[o] = v;
        outH[o] = __float2half_rn(v);
    }
}

__global__ void unbuild_kernel(const float* __restrict__ in, float* __restrict__ out) {
    __shared__ float tile[32][33];
    int n  = blockIdx.z;
    int c0 = blockIdx.y * 32;
    int l0 = blockIdx.x * 32;
    int tx = threadIdx.x, ty = threadIdx.y;
#pragma unroll
    for (int i = 0; i < 4; i++) {
        int l = l0 + ty + i * 8;
        int c = c0 + tx;
        tile[ty + i * 8][tx] = in[((size_t)n * LL + l) * CD + c];
    }
    __syncthreads();
#pragma unroll
    for (int i = 0; i < 4; i++) {
        int c = c0 + ty + i * 8;
        int l = l0 + tx;
        out[((size_t)n * CD + c) * LL + l] = tile[tx][ty + i * 8];
    }
}

// ---------------- FP16 tensor-core GEMM (m16n8k16, f32 accum), BK=32 ----------------
// C[M,N] = epi( A' @ B ), B fp16 k-pair interleaved ([K/2][N] 32-bit words).
// qkvMode=0: A' = [A|A2] concat over K.   qkvMode=1: A' = (colBase<256 ? A : A2).
// BM=BN=128, BK=32 (two k16 subtiles per stage), 8 warps, warp tile 32x64.
#define ASW32 20               // A row stride in words (32 halves = 16 words + 4 pad)
#define BSW32 136              // B k-pair row stride in words (128 + 8 pad)
#define AS32_WORDS (128 * ASW32)   // 2560
#define BS32_WORDS (16 * BSW32)    // 2176

__device__ __forceinline__ void cp16(void* dst, const void* src) {
    uint32_t d = (uint32_t)__cvta_generic_to_shared(dst);
    asm volatile("cp.async.cg.shared.global [%0], [%1], 16;\n" :: "r"(d), "l"(src));
}

__global__ __launch_bounds__(256, 2) void hgemm_kernel(
    const __half* __restrict__ A, const __half* __restrict__ A2,
    const __half* __restrict__ B, void* __restrict__ Cout,
    int M, int Ktot, int K1, int N, int epi, int outHalf, int qkvMode)
{
    __shared__ uint32_t As2[2][AS32_WORDS];
    __shared__ uint32_t Bs2[2][BS32_WORDS];

    int tid = threadIdx.x;
    int warp = tid >> 5;
    int lane = tid & 31;
    int g = lane >> 2;
    int q = lane & 3;
    int rowBase = blockIdx.y * 128;
    int colBase = blockIdx.x * 128;
    int wm0 = (warp >> 1) * 32;
    int wn0 = (warp & 1) * 64;
    int K2 = Ktot - K1;
    int NS = Ktot >> 5;            // stages of 32 k

    int myEpi = epi;
    const __half* Abase = A;
    if (qkvMode) {
        myEpi = (colBase < 512) ? EPI_ELU1 : EPI_NONE;
        Abase = (colBase < 256) ? A : A2;
    }

    float acc[2][8][4];
#pragma unroll
    for (int mt = 0; mt < 2; mt++)
#pragma unroll
        for (int nt = 0; nt < 8; nt++)
#pragma unroll
            for (int r = 0; r < 4; r++) acc[mt][nt][r] = 0.0f;

    // A: 512 chunks of 16B: c = tid, tid+256 -> row = c>>2, j = c&3 (8 halves each)
    int aRow0 = tid >> 2,          aJ0 = tid & 3;
    int aRow1 = (tid + 256) >> 2,  aJ1 = tid & 3;   // (tid+256)&3 == tid&3
    // B: 512 chunks: c = tid, tid+256 -> kpair row = c>>5 (0..15), word col = (c&31)*4
    int bR = tid >> 5, bC = (tid & 31) << 2;        // rows bR and bR+8

    auto issue = [&](int s, int buf) {
        int k0 = s << 5;
        int kk0 = k0 + aJ0 * 8;
        int kk1 = k0 + aJ1 * 8;
        const __half *srcA0, *srcA1;
        if (qkvMode) {
            srcA0 = Abase + (size_t)(rowBase + aRow0) * K1 + kk0;
            srcA1 = Abase + (size_t)(rowBase + aRow1) * K1 + kk1;
        } else {
            srcA0 = (kk0 < K1) ? (A  + (size_t)(rowBase + aRow0) * K1 + kk0)
                               : (A2 + (size_t)(rowBase + aRow0) * K2 + (kk0 - K1));
            srcA1 = (kk1 < K1) ? (A  + (size_t)(rowBase + aRow1) * K1 + kk1)
                               : (A2 + (size_t)(rowBase + aRow1) * K2 + (kk1 - K1));
        }
        cp16(&As2[buf][aRow0 * ASW32 + aJ0 * 4], srcA0);
        cp16(&As2[buf][aRow1 * ASW32 + aJ1 * 4], srcA1);
        const uint32_t* Bw = (const uint32_t*)B;
        cp16(&Bs2[buf][bR * BSW32 + bC],
             Bw + (size_t)(s * 16 + bR) * N + colBase + bC);
        cp16(&Bs2[buf][(bR + 8) * BSW32 + bC],
             Bw + (size_t)(s * 16 + bR + 8) * N + colBase + bC);
    };

    issue(0, 0);
    asm volatile("cp.async.commit_group;\n");

    int buf = 0;
    for (int s = 0; s < NS; s++) {
        if (s + 1 < NS) {
            issue(s + 1, buf ^ 1);
            asm volatile("cp.async.commit_group;\n");
            asm volatile("cp.async.wait_group 1;\n");
        } else {
            asm volatile("cp.async.wait_group 0;\n");
        }
        __syncthreads();

        const uint32_t* AsB = As2[buf];
        const uint32_t* BsB = Bs2[buf];
#pragma unroll
        for (int ks = 0; ks < 2; ks++) {
            uint32_t af[2][4];
#pragma unroll
            for (int mt = 0; mt < 2; mt++) {
                int m = wm0 + mt * 16;
                af[mt][0] = AsB[(m + g    ) * ASW32 + ks * 8 + q    ];
                af[mt][1] = AsB[(m + g + 8) * ASW32 + ks * 8 + q    ];
                af[mt][2] = AsB[(m + g    ) * ASW32 + ks * 8 + q + 4];
                af[mt][3] = AsB[(m + g + 8) * ASW32 + ks * 8 + q + 4];
            }
            uint32_t bf[8][2];
#pragma unroll
            for (int nt = 0; nt < 8; nt++) {
                int n = wn0 + nt * 8 + g;
                bf[nt][0] = BsB[(ks * 8 + q    ) * BSW32 + n];
                bf[nt][1] = BsB[(ks * 8 + q + 4) * BSW32 + n];
            }
#pragma unroll
            for (int mt = 0; mt < 2; mt++)
#pragma unroll
                for (int nt = 0; nt < 8; nt++) {
                    asm volatile(
                        "mma.sync.aligned.m16n8k16.row.col.f32.f16.f16.f32 "
                        "{%0,%1,%2,%3}, {%4,%5,%6,%7}, {%8,%9}, {%0,%1,%2,%3};\n"
                        : "+f"(acc[mt][nt][0]), "+f"(acc[mt][nt][1]),
                          "+f"(acc[mt][nt][2]), "+f"(acc[mt][nt][3])
                        : "r"(af[mt][0]), "r"(af[mt][1]), "r"(af[mt][2]), "r"(af[mt][3]),
                          "r"(bf[nt][0]), "r"(bf[nt][1]));
                }
        }
        buf ^= 1;
        __syncthreads();
    }

#pragma unroll
    for (int mt = 0; mt < 2; mt++) {
        int row = rowBase + wm0 + mt * 16 + g;
#pragma unroll
        for (int nt = 0; nt < 8; nt++) {
            int col = colBase + wn0 + nt * 8 + 2 * q;
            float v0 = acc[mt][nt][0], v1 = acc[mt][nt][1];
            float v2 = acc[mt][nt][2], v3 = acc[mt][nt][3];
            if (myEpi == EPI_ELU1) {
                v0 = (v0 > 0.f) ? v0 + 1.f : expf(v0);
                v1 = (v1 > 0.f) ? v1 + 1.f : expf(v1);
                v2 = (v2 > 0.f) ? v2 + 1.f : expf(v2);
                v3 = (v3 > 0.f) ? v3 + 1.f : expf(v3);
            } else if (myEpi == EPI_RELU) {
                v0 = fmaxf(v0, 0.f); v1 = fmaxf(v1, 0.f);
                v2 = fmaxf(v2, 0.f); v3 = fmaxf(v3, 0.f);
            }
            if (outHalf) {
                __half* Ch = (__half*)Cout;
                *(__half2*)(Ch + (size_t)row * N + col)       = __floats2half2_rn(v0, v1);
                *(__half2*)(Ch + (size_t)(row + 8) * N + col) = __floats2half2_rn(v2, v3);
            } else {
                float* Cf = (float*)Cout;
                *(float2*)(Cf + (size_t)row * N + col)       = make_float2(v0, v1);
                *(float2*)(Cf + (size_t)(row + 8) * N + col) = make_float2(v2, v3);
            }
        }
    }
}

// ---------------- Fused GEMM + LayerNorm (BM=64, BN=256, K=256) ----------------
// residual=0: OutH = fp16( LN(A @ B) )          (merge + LN1); A row stride sA halves
// residual=1: F0 += LN(A @ B); F0h = fp16(F0)   (FFN2 + LN2 + residual)
#define LASW 12
#define LBSW 264

__global__ __launch_bounds__(256, 2) void hgemm_ln_kernel(
    const __half* __restrict__ A, int sA, const __half* __restrict__ B,
    __half* __restrict__ OutH,
    float* __restrict__ F0, __half* __restrict__ F0h,
    const float* __restrict__ gam, const float* __restrict__ bet,
    int residual)
{
    __shared__ uint32_t As2[2][64 * LASW];
    __shared__ uint32_t Bs2[2][8 * LBSW];
    __shared__ float sg[256], sb[256];
    __shared__ float srs[64], ssq[64];

    int tid = threadIdx.x;
    int warp = tid >> 5;
    int lane = tid & 31;
    int g = lane >> 2;
    int q = lane & 3;
    int rowBase = blockIdx.x * 64;
    int wm0 = (warp >> 2) * 32;     // 2 warps in M
    int wn0 = (warp & 3) * 64;      // 4 warps in N
    const int NS = 16;              // K = 256

    sg[tid] = gam[tid];
    sb[tid] = bet[tid];
    if (tid < 64) { srs[tid] = 0.0f; ssq[tid] = 0.0f; }

    float acc[2][8][4];
#pragma unroll
    for (int mt = 0; mt < 2; mt++)
#pragma unroll
        for (int nt = 0; nt < 8; nt++)
#pragma unroll
            for (int r = 0; r < 4; r++) acc[mt][nt][r] = 0.0f;

    int aRow = tid >> 1, aJ = tid & 1;
    int bR0 = tid >> 6,         bC0 = (tid & 63) << 2;
    int bR1 = (tid + 256) >> 6, bC1 = bC0;

    auto issue = [&](int s, int buf) {
        int k0 = s << 4;
        if (tid < 128)
            cp16(&As2[buf][aRow * LASW + aJ * 4],
                 A + (size_t)(rowBase + aRow) * sA + k0 + aJ * 8);
        const uint32_t* Bw = (const uint32_t*)B;
        cp16(&Bs2[buf][bR0 * LBSW + bC0], Bw + (size_t)(s * 8 + bR0) * 256 + bC0);
        cp16(&Bs2[buf][bR1 * LBSW + bC1], Bw + (size_t)(s * 8 + bR1) * 256 + bC1);
    };

    issue(0, 0);
    asm volatile("cp.async.commit_group;\n");

    int buf = 0;
    for (int s = 0; s < NS; s++) {
        if (s + 1 < NS) {
            issue(s + 1, buf ^ 1);
            asm volatile("cp.async.commit_group;\n");
            asm volatile("cp.async.wait_group 1;\n");
        } else {
            asm volatile("cp.async.wait_group 0;\n");
        }
        __syncthreads();

        const uint32_t* AsB = As2[buf];
        const uint32_t* BsB = Bs2[buf];
        uint32_t af[2][4];
#pragma unroll
        for (int mt = 0; mt < 2; mt++) {
            int m = wm0 + mt * 16;
            af[mt][0] = AsB[(m + g    ) * LASW + q    ];
            af[mt][1] = AsB[(m + g + 8) * LASW + q    ];
            af[mt][2] = AsB[(m + g    ) * LASW + q + 4];
            af[mt][3] = AsB[(m + g + 8) * LASW + q + 4];
        }
        uint32_t bf[8][2];
#pragma unroll
        for (int nt = 0; nt < 8; nt++) {
            int n = wn0 + nt * 8 + g;
            bf[nt][0] = BsB[q       * LBSW + n];
            bf[nt][1] = BsB[(q + 4) * LBSW + n];
        }
#pragma unroll
        for (int mt = 0; mt < 2; mt++)
#pragma unroll
            for (int nt = 0; nt < 8; nt++) {
                asm volatile(
                    "mma.sync.aligned.m16n8k16.row.col.f32.f16.f16.f32 "
                    "{%0,%1,%2,%3}, {%4,%5,%6,%7}, {%8,%9}, {%0,%1,%2,%3};\n"
                    : "+f"(acc[mt][nt][0]), "+f"(acc[mt][nt][1]),
                      "+f"(acc[mt][nt][2]), "+f"(acc[mt][nt][3])
                    : "r"(af[mt][0]), "r"(af[mt][1]), "r"(af[mt][2]), "r"(af[mt][3]),
                      "r"(bf[nt][0]), "r"(bf[nt][1]));
            }
        buf ^= 1;
        __syncthreads();
    }

    // ---- LayerNorm epilogue ----
#pragma unroll
    for (int mt = 0; mt < 2; mt++) {
#pragma unroll
        for (int hr = 0; hr < 2; hr++) {
            int rl = wm0 + mt * 16 + hr * 8 + g;
            float s1 = 0.0f, s2 = 0.0f;
#pragma unroll
            for (int nt = 0; nt < 8; nt++) {
                float v0 = acc[mt][nt][hr * 2], v1 = acc[mt][nt][hr * 2 + 1];
                s1 += v0 + v1;
                s2 += v0 * v0 + v1 * v1;
            }
            s1 += __shfl_xor_sync(0xffffffffu, s1, 1);
            s1 += __shfl_xor_sync(0xffffffffu, s1, 2);
            s2 += __shfl_xor_sync(0xffffffffu, s2, 1);
            s2 += __shfl_xor_sync(0xffffffffu, s2, 2);
            if (q == 0) {
                atomicAdd(&srs[rl], s1);
                atomicAdd(&ssq[rl], s2);
            }
        }
    }
    __syncthreads();

#pragma unroll
    for (int mt = 0; mt < 2; mt++) {
#pragma unroll
        for (int hr = 0; hr < 2; hr++) {
            int rl = wm0 + mt * 16 + hr * 8 + g;
            int row = rowBase + rl;
            float mu = srs[rl] * (1.0f / 256.0f);
            float var = ssq[rl] * (1.0f / 256.0f) - mu * mu;
            float rstd = rsqrtf(var + 1e-5f);
#pragma unroll
            for (int nt = 0; nt < 8; nt++) {
                int col = wn0 + nt * 8 + 2 * q;
                float v0 = (acc[mt][nt][hr * 2]     - mu) * rstd * sg[col]     + sb[col];
                float v1 = (acc[mt][nt][hr * 2 + 1] - mu) * rstd * sg[col + 1] + sb[col + 1];
                size_t o = (size_t)row * 256 + col;
                if (residual) {
                    float2 f = *(float2*)(F0 + o);
                    f.x += v0; f.y += v1;
                    *(float2*)(F0 + o) = f;
                    *(__half2*)(F0h + o) = __floats2half2_rn(f.x, f.y);
                } else {
                    *(__half2*)(OutH + o) = __floats2half2_rn(v0, v1);
                }
            }
        }
    }
}

// ---------------- KV = sum_s K[s,d]*v[s,e], Ksum per (n,h); QKV layout stride 768 ----------------
#define KV_CHUNKS 20
#define KV_SC (LL / KV_CHUNKS)
__global__ void kv_reduce_kernel(const __half* __restrict__ QKV,
                                 float* __restrict__ KV, float* __restrict__ KS) {
    int nh = blockIdx.x;
    int n = nh >> 3, h = nh & 7;
    int t = threadIdx.x;
    int d = t & 31;
    int eg = t >> 5;
    int s0 = blockIdx.y * KV_SC;
    float a0 = 0, a1 = 0, a2 = 0, a3 = 0, ks = 0;
    for (int s = s0; s < s0 + KV_SC; s++) {
        size_t rowb = (size_t)(n * LL + s) * 768 + h * HDD;
        float kd = __half2float(QKV[rowb + 256 + d]);
        const __half2* vp = (const __half2*)(QKV + rowb + 512 + eg * 4);
        float2 f0 = __half22float2(vp[0]);
        float2 f1 = __half22float2(vp[1]);
        a0 = fmaf(kd, f0.x, a0);
        a1 = fmaf(kd, f0.y, a1);
        a2 = fmaf(kd, f1.x, a2);
        a3 = fmaf(kd, f1.y, a3);
        ks += kd;
    }
    float* kvp = KV + ((size_t)nh * HDD + d) * HDD + eg * 4;
    atomicAdd(kvp + 0, a0);
    atomicAdd(kvp + 1, a1);
    atomicAdd(kvp + 2, a2);
    atomicAdd(kvp + 3, a3);
    if (eg == 0) atomicAdd(KS + nh * HDD + d, ks);
}

// ---------------- attn: Q region of QKV (stride 768) updated in place ----------------
#define AT_CHUNKS 40
#define AT_RPB (LL / AT_CHUNKS)
__global__ void attn_apply_kernel(__half* __restrict__ QKV, const float* __restrict__ KV,
                                  const float* __restrict__ KS) {
    __shared__ float kvs[32][33];
    __shared__ float kss[32];
    int n = blockIdx.z, h = blockIdx.y;
    int nh = n * NHD + h;
    int t = threadIdx.x, lane = t & 31, w = t >> 5;
    for (int i = t; i < 1024; i += 256) kvs[i >> 5][i & 31] = KV[(size_t)nh * 1024 + i];
    if (t < 32) kss[t] = KS[nh * 32 + t];
    __syncthreads();
    int l0 = blockIdx.x * AT_RPB + w * (AT_RPB / 8);
    for (int r = 0; r < AT_RPB / 8; r++) {
        int l = l0 + r;
        size_t base = (size_t)(n * LL + l) * 768 + h * HDD;
        float qd = __half2float(QKV[base + lane]);
        float zs = qd * kss[lane];
#pragma unroll
        for (int o = 16; o; o >>= 1) zs += __shfl_xor_sync(0xffffffffu, zs, o);
        float z = 1.0f / (zs + 1e-6f);
        float acc = 0.0f;
#pragma unroll
        for (int d = 0; d < 32; d++) {
            float qv = __shfl_sync(0xffffffffu, qd, d);
            acc = fmaf(qv, kvs[d][lane], acc);
        }
        QKV[base + lane] = __float2half_rn(acc * z);
    }
}

// ---------------- launch ----------------
extern "C" void kernel_launch(void* const* d_in, const int* in_sizes, int n_in,
                              void* d_out, int out_size) {
    const float* feat0 = (const float*)d_in[0];
    const float* feat1 = (const float*)d_in[1];
    const float* Wq = (const float*)d_in[2];
    const float* Wk = (const float*)d_in[3];
    const float* Wv = (const float*)d_in[4];
    const float* Wm = (const float*)d_in[5];
    const float* W1 = (const float*)d_in[6];
    const float* W2 = (const float*)d_in[7];
    const float* g1 = (const float*)d_in[8];
    const float* b1 = (const float*)d_in[9];
    const float* g2 = (const float*)d_in[10];
    const float* b2 = (const float*)d_in[11];

    float *F0, *KVS, *PE;
    __half *F0h, *F1h, *QKVh, *Mh, *Hh;
    __half *wQKV, *wM, *w1p, *w2p;
    cudaGetSymbolAddress((void**)&F0,   g_F0);
    cudaGetSymbolAddress((void**)&KVS,  g_KVS);
    cudaGetSymbolAddress((void**)&PE,   g_PE);
    cudaGetSymbolAddress((void**)&F0h,  g_F0h);
    cudaGetSymbolAddress((void**)&F1h,  g_F1h);
    cudaGetSymbolAddress((void**)&QKVh, g_QKVh);
    cudaGetSymbolAddress((void**)&Mh,   g_Mh);
    cudaGetSymbolAddress((void**)&Hh,   g_Hh);
    cudaGetSymbolAddress((void**)&wQKV, g_Wqkv);
    cudaGetSymbolAddress((void**)&wM,   g_WmH);
    cudaGetSymbolAddress((void**)&w1p,  g_W1H);
    cudaGetSymbolAddress((void**)&w2p,  g_W2H);
    float* KV = KVS;
    float* KS = KVS + KVS_KV_SZ;

    weight_prep_kernel<<<(2 * 2 * CD * CD + 255) / 256, 256>>>(Wq, Wk, Wv, Wm, W1, W2);
    pe_precompute_kernel<<<(CD * LL + 255) / 256, 256>>>(PE);

    dim3 tb(32, 8);
    dim3 tg(LL / 32, CD / 32, NB);
    build_pe_kernel<<<tg, tb>>>(feat0, PE, F0, F0h);
    build_pe_kernel<<<tg, tb>>>(feat1, PE, nullptr, F1h);

    dim3 ggQKV(6, MR / 128);   // N=768
    dim3 gg(CD / 128, MR / 128);
    const int GLN = MR / 64;

    for (int i = 0; i < 2; i++) {
        const __half* wqkv = wQKV + (size_t)i * CD * 3 * CD;
        const __half* wm = wM + (size_t)i * CD * CD;
        const __half* w1 = w1p + (size_t)i * 2 * CD * CD;
        const __half* w2 = w2p + (size_t)i * CD * CD;

        // fused Q|K|V projection: QKVh[MR][768]
        hgemm_kernel<<<ggQKV, 256>>>(F0h, F1h, wqkv, QKVh,
                                     MR, CD, CD, 3 * CD, EPI_QKV, 1, 1);

        cudaMemsetAsync(KVS, 0, sizeof(float) * NB * NHD * (HDD * HDD + HDD), 0);
        kv_reduce_kernel<<<dim3(NB * NHD, KV_CHUNKS), 256>>>(QKVh, KV, KS);

        // attention apply in place on Q region
        attn_apply_kernel<<<dim3(AT_CHUNKS, NHD, NB), 256>>>(QKVh, KV, KS);

        // merge + LN1 fused: Mh = fp16( LN(Q @ Wm) )   (A stride 768)
        hgemm_ln_kernel<<<GLN, 256>>>(QKVh, 768, wm, Mh, nullptr, nullptr,
                                      g1 + i * CD, b1 + i * CD, 0);

        // FFN1: relu([F0h|Mh] @ W1) -> Hh (fp16)
        hgemm_kernel<<<gg, 256>>>(F0h, Mh, w1, Hh, MR, 2 * CD, CD, CD, EPI_RELU, 1, 0);

        // FFN2 + LN2 + residual fused: F0 += LN(Hh @ W2); F0h = fp16(F0)
        hgemm_ln_kernel<<<GLN, 256>>>(Hh, 256, w2, nullptr, F0, F0h,
                                      g2 + i * CD, b2 + i * CD, 1);
    }

    unbuild_kernel<<<tg, tb>>>(F0, (float*)d_out);
}

// round 17
// speedup vs baseline: 1.1684x; 1.0125x over previous
#include <cuda_runtime.h>
#include <cuda_fp16.h>
#include <cstdint>

// Problem constants
#define NB    16
#define CD    256
#define HH    80
#define WW    60
#define LL    4800            // HH*WW
#define NHD   8
#define HDD   32
#define MR    (NB*LL)         // 76800 rows

#define EPI_NONE 0
#define EPI_ELU1 1
#define EPI_RELU 2
#define EPI_QKV  3            // ELU1 for cols < 512, NONE for cols >= 512

// ---------------- scratch (static device globals; no allocation) ----------------
__device__ float  g_F0  [(size_t)MR * CD];     // exact x (residual/output)
__device__ __half g_F0h [(size_t)MR * CD];
__device__ __half g_F1h [(size_t)MR * CD];
__device__ __half g_QKVh[(size_t)MR * 3 * CD]; // [MR][768]: Q|K|V
__device__ __half g_Mh  [(size_t)MR * CD];     // merge+LN1 output
__device__ __half g_Hh  [(size_t)MR * CD];     // FFN1 output
__device__ float  g_PE  [(size_t)CD * LL];
__device__ float  g_KVS [NB * NHD * (HDD * HDD + HDD)];  // KV then KS
#define KVS_KV_SZ (NB * NHD * HDD * HDD)
// fp16 weights, k-pair interleaved: WH[((k>>1)*N + n)*2 + (k&1)] = W[k][n]
__device__ __half g_Wqkv[2 * CD * 3 * CD];     // [128][768][2] per layer
__device__ __half g_WmH [2 * CD * CD];
__device__ __half g_W1H [2 * 2 * CD * CD];
__device__ __half g_W2H [2 * CD * CD];

// ---------------- weight prep: fp16 + k-pair interleave ----------------
__global__ void weight_prep_kernel(
    const float* __restrict__ wq, const float* __restrict__ wk,
    const float* __restrict__ wv, const float* __restrict__ wm,
    const float* __restrict__ w1, const float* __restrict__ w2)
{
    int i = blockIdx.x * blockDim.x + threadIdx.x;
    const int S = 2 * CD * CD;              // 131072
    if (i < S) {
        int li = i >> 16;                   // CD*CD = 65536
        int r  = i & 65535;
        int k = r >> 8, n = r & 255;
        int kp = ((k >> 1) * 768) * 2 + (k & 1);
        int base = li * 196608;
        g_Wqkv[base + kp + (n      ) * 2] = __float2half_rn(wq[i]);
        g_Wqkv[base + kp + (n + 256) * 2] = __float2half_rn(wk[i]);
        g_Wqkv[base + kp + (n + 512) * 2] = __float2half_rn(wv[i]);
        int dst = li * 65536 + (((k >> 1) << 8) + n) * 2 + (k & 1);
        g_WmH[dst] = __float2half_rn(wm[i]);
        g_W2H[dst] = __float2half_rn(w2[i]);
    }
    if (i < 2 * S) {                        // W1: [512][256] per layer
        int li = i >> 17;
        int r  = i & 131071;
        int k = r >> 8, n = r & 255;
        int dst = li * 131072 + (((k >> 1) << 8) + n) * 2 + (k & 1);
        g_W1H[dst] = __float2half_rn(w1[i]);
    }
}

// ---------------- positional encoding ----------------
// fac = (-log(1e4)/256)//2 == -1.0  =>  div[j] = exp(-2*j)
__global__ void pe_precompute_kernel(float* __restrict__ PE) {
    int idx = blockIdx.x * blockDim.x + threadIdx.x;
    if (idx >= CD * LL) return;
    int c = idx / LL, l = idx % LL;
    int j = c >> 2, r = c & 3;
    int h = l / WW, w = l % WW;
    float f = expf(-2.0f * (float)j);
    float pos = (r < 2) ? (float)(w + 1) : (float)(h + 1);
    float arg = pos * f;
    PE[idx] = (r & 1) ? cosf(arg) : sinf(arg);
}

// NCHW -> [N,L,C] with PE; writes optional f32 + fp16
__global__ void build_pe_kernel(const float* __restrict__ feat, const float* __restrict__ PE,
                                float* __restrict__ outF, __half* __restrict__ outH) {
    __shared__ float tile[32][33];
    int n  = blockIdx.z;
    int c0 = blockIdx.y * 32;
    int l0 = blockIdx.x * 32;
    int tx = threadIdx.x, ty = threadIdx.y;
#pragma unroll
    for (int i = 0; i < 4; i++) {
        int c = c0 + ty + i * 8;
        int l = l0 + tx;
        tile[ty + i * 8][tx] = feat[((size_t)n * CD + c) * LL + l] + PE[(size_t)c * LL + l];
    }
    __syncthreads();
#pragma unroll
    for (int i = 0; i < 4; i++) {
        int l = l0 + ty + i * 8;
        int c = c0 + tx;
        float v = tile[tx][ty + i * 8];
        size_t o = ((size_t)n * LL + l) * CD + c;
        if (outF) outF[o] = v;
        outH[o] = __float2half_rn(v);
    }
}

__global__ void unbuild_kernel(const float* __restrict__ in, float* __restrict__ out) {
    __shared__ float tile[32][33];
    int n  = blockIdx.z;
    int c0 = blockIdx.y * 32;
    int l0 = blockIdx.x * 32;
    int tx = threadIdx.x, ty = threadIdx.y;
#pragma unroll
    for (int i = 0; i < 4; i++) {
        int l = l0 + ty + i * 8;
        int c = c0 + tx;
        tile[ty + i * 8][tx] = in[((size_t)n * LL + l) * CD + c];
    }
    __syncthreads();
#pragma unroll
    for (int i = 0; i < 4; i++) {
        int c = c0 + ty + i * 8;
        int l = l0 + tx;
        out[((size_t)n * CD + c) * LL + l] = tile[tx][ty + i * 8];
    }
}

// ---------------- FP16 tensor-core GEMM (m16n8k16, f32 accum), BK=32 ----------------
// C[M,N] = epi( A' @ B ), B fp16 k-pair interleaved ([K/2][N] 32-bit words).
// qkvMode=0: A' = [A|A2] concat over K.   qkvMode=1: A' = (colBase<256 ? A : A2).
// BM=BN=128, BK=32 (two k16 subtiles per stage), 8 warps, warp tile 32x64.
#define ASW32 20               // A row stride in words (32 halves = 16 words + 4 pad)
#define BSW32 136              // B k-pair row stride in words (128 + 8 pad)
#define AS32_WORDS (128 * ASW32)   // 2560
#define BS32_WORDS (16 * BSW32)    // 2176

__device__ __forceinline__ void cp16(void* dst, const void* src) {
    uint32_t d = (uint32_t)__cvta_generic_to_shared(dst);
    asm volatile("cp.async.cg.shared.global [%0], [%1], 16;\n" :: "r"(d), "l"(src));
}

__global__ __launch_bounds__(256, 2) void hgemm_kernel(
    const __half* __restrict__ A, const __half* __restrict__ A2,
    const __half* __restrict__ B, void* __restrict__ Cout,
    int M, int Ktot, int K1, int N, int epi, int outHalf, int qkvMode)
{
    __shared__ uint32_t As2[2][AS32_WORDS];
    __shared__ uint32_t Bs2[2][BS32_WORDS];

    int tid = threadIdx.x;
    int warp = tid >> 5;
    int lane = tid & 31;
    int g = lane >> 2;
    int q = lane & 3;
    int rowBase = blockIdx.y * 128;
    int colBase = blockIdx.x * 128;
    int wm0 = (warp >> 1) * 32;
    int wn0 = (warp & 1) * 64;
    int K2 = Ktot - K1;
    int NS = Ktot >> 5;            // stages of 32 k

    int myEpi = epi;
    const __half* Abase = A;
    if (qkvMode) {
        myEpi = (colBase < 512) ? EPI_ELU1 : EPI_NONE;
        Abase = (colBase < 256) ? A : A2;
    }

    float acc[2][8][4];
#pragma unroll
    for (int mt = 0; mt < 2; mt++)
#pragma unroll
        for (int nt = 0; nt < 8; nt++)
#pragma unroll
            for (int r = 0; r < 4; r++) acc[mt][nt][r] = 0.0f;

    // A: 512 chunks of 16B: c = tid, tid+256 -> row = c>>2, j = c&3 (8 halves each)
    int aRow0 = tid >> 2,          aJ0 = tid & 3;
    int aRow1 = (tid + 256) >> 2,  aJ1 = tid & 3;
    // B: 512 chunks: c = tid, tid+256 -> kpair row = c>>5 (0..15), word col = (c&31)*4
    int bR = tid >> 5, bC = (tid & 31) << 2;

    auto issue = [&](int s, int buf) {
        int k0 = s << 5;
        int kk0 = k0 + aJ0 * 8;
        int kk1 = k0 + aJ1 * 8;
        const __half *srcA0, *srcA1;
        if (qkvMode) {
            srcA0 = Abase + (size_t)(rowBase + aRow0) * K1 + kk0;
            srcA1 = Abase + (size_t)(rowBase + aRow1) * K1 + kk1;
        } else {
            srcA0 = (kk0 < K1) ? (A  + (size_t)(rowBase + aRow0) * K1 + kk0)
                               : (A2 + (size_t)(rowBase + aRow0) * K2 + (kk0 - K1));
            srcA1 = (kk1 < K1) ? (A  + (size_t)(rowBase + aRow1) * K1 + kk1)
                               : (A2 + (size_t)(rowBase + aRow1) * K2 + (kk1 - K1));
        }
        cp16(&As2[buf][aRow0 * ASW32 + aJ0 * 4], srcA0);
        cp16(&As2[buf][aRow1 * ASW32 + aJ1 * 4], srcA1);
        const uint32_t* Bw = (const uint32_t*)B;
        cp16(&Bs2[buf][bR * BSW32 + bC],
             Bw + (size_t)(s * 16 + bR) * N + colBase + bC);
        cp16(&Bs2[buf][(bR + 8) * BSW32 + bC],
             Bw + (size_t)(s * 16 + bR + 8) * N + colBase + bC);
    };

    issue(0, 0);
    asm volatile("cp.async.commit_group;\n");

    int buf = 0;
    for (int s = 0; s < NS; s++) {
        if (s + 1 < NS) {
            issue(s + 1, buf ^ 1);
            asm volatile("cp.async.commit_group;\n");
            asm volatile("cp.async.wait_group 1;\n");
        } else {
            asm volatile("cp.async.wait_group 0;\n");
        }
        __syncthreads();

        const uint32_t* AsB = As2[buf];
        const uint32_t* BsB = Bs2[buf];
#pragma unroll
        for (int ks = 0; ks < 2; ks++) {
            uint32_t af[2][4];
#pragma unroll
            for (int mt = 0; mt < 2; mt++) {
                int m = wm0 + mt * 16;
                af[mt][0] = AsB[(m + g    ) * ASW32 + ks * 8 + q    ];
                af[mt][1] = AsB[(m + g + 8) * ASW32 + ks * 8 + q    ];
                af[mt][2] = AsB[(m + g    ) * ASW32 + ks * 8 + q + 4];
                af[mt][3] = AsB[(m + g + 8) * ASW32 + ks * 8 + q + 4];
            }
            uint32_t bf[8][2];
#pragma unroll
            for (int nt = 0; nt < 8; nt++) {
                int n = wn0 + nt * 8 + g;
                bf[nt][0] = BsB[(ks * 8 + q    ) * BSW32 + n];
                bf[nt][1] = BsB[(ks * 8 + q + 4) * BSW32 + n];
            }
#pragma unroll
            for (int mt = 0; mt < 2; mt++)
#pragma unroll
                for (int nt = 0; nt < 8; nt++) {
                    asm volatile(
                        "mma.sync.aligned.m16n8k16.row.col.f32.f16.f16.f32 "
                        "{%0,%1,%2,%3}, {%4,%5,%6,%7}, {%8,%9}, {%0,%1,%2,%3};\n"
                        : "+f"(acc[mt][nt][0]), "+f"(acc[mt][nt][1]),
                          "+f"(acc[mt][nt][2]), "+f"(acc[mt][nt][3])
                        : "r"(af[mt][0]), "r"(af[mt][1]), "r"(af[mt][2]), "r"(af[mt][3]),
                          "r"(bf[nt][0]), "r"(bf[nt][1]));
                }
        }
        buf ^= 1;
        __syncthreads();
    }

#pragma unroll
    for (int mt = 0; mt < 2; mt++) {
        int row = rowBase + wm0 + mt * 16 + g;
#pragma unroll
        for (int nt = 0; nt < 8; nt++) {
            int col = colBase + wn0 + nt * 8 + 2 * q;
            float v0 = acc[mt][nt][0], v1 = acc[mt][nt][1];
            float v2 = acc[mt][nt][2], v3 = acc[mt][nt][3];
            if (myEpi == EPI_ELU1) {
                v0 = (v0 > 0.f) ? v0 + 1.f : expf(v0);
                v1 = (v1 > 0.f) ? v1 + 1.f : expf(v1);
                v2 = (v2 > 0.f) ? v2 + 1.f : expf(v2);
                v3 = (v3 > 0.f) ? v3 + 1.f : expf(v3);
            } else if (myEpi == EPI_RELU) {
                v0 = fmaxf(v0, 0.f); v1 = fmaxf(v1, 0.f);
                v2 = fmaxf(v2, 0.f); v3 = fmaxf(v3, 0.f);
            }
            if (outHalf) {
                __half* Ch = (__half*)Cout;
                *(__half2*)(Ch + (size_t)row * N + col)       = __floats2half2_rn(v0, v1);
                *(__half2*)(Ch + (size_t)(row + 8) * N + col) = __floats2half2_rn(v2, v3);
            } else {
                float* Cf = (float*)Cout;
                *(float2*)(Cf + (size_t)row * N + col)       = make_float2(v0, v1);
                *(float2*)(Cf + (size_t)(row + 8) * N + col) = make_float2(v2, v3);
            }
        }
    }
}

// ---------------- Fused GEMM + LayerNorm (BM=64, BN=256, K=256), BK=32 ----------------
// residual=0: OutH = fp16( LN(A @ B) )          (merge + LN1); A row stride sA halves
// residual=1: F0 += LN(A @ B); F0h = fp16(F0)   (FFN2 + LN2 + residual)
#define LASW32 20              // A row stride in words (32 halves + pad)
#define LBSW32 264             // B k-pair row stride in words (256 + 8 pad)
#define LNA_W (64 * LASW32)    // 1280 words per stage
#define LNB_W (16 * LBSW32)    // 4224 words per stage

__global__ __launch_bounds__(256, 2) void hgemm_ln_kernel(
    const __half* __restrict__ A, int sA, const __half* __restrict__ B,
    __half* __restrict__ OutH,
    float* __restrict__ F0, __half* __restrict__ F0h,
    const float* __restrict__ gam, const float* __restrict__ bet,
    int residual)
{
    __shared__ uint32_t As2[2][LNA_W];
    __shared__ uint32_t Bs2[2][LNB_W];
    __shared__ float sg[256], sb[256];
    __shared__ float srs[64], ssq[64];

    int tid = threadIdx.x;
    int warp = tid >> 5;
    int lane = tid & 31;
    int g = lane >> 2;
    int q = lane & 3;
    int rowBase = blockIdx.x * 64;
    int wm0 = (warp >> 2) * 32;     // 2 warps in M
    int wn0 = (warp & 3) * 64;      // 4 warps in N
    const int NS = 8;               // K = 256, stages of 32

    sg[tid] = gam[tid];
    sb[tid] = bet[tid];
    if (tid < 64) { srs[tid] = 0.0f; ssq[tid] = 0.0f; }

    float acc[2][8][4];
#pragma unroll
    for (int mt = 0; mt < 2; mt++)
#pragma unroll
        for (int nt = 0; nt < 8; nt++)
#pragma unroll
            for (int r = 0; r < 4; r++) acc[mt][nt][r] = 0.0f;

    // A: 256 chunks (1/thread): row = tid>>2, j = tid&3
    int aRow = tid >> 2, aJ = tid & 3;
    // B: 1024 chunks (4/thread): c = tid + 256p -> kpair row = c>>6, word col = (c&63)*4
    int bR = tid >> 6, bC = (tid & 63) << 2;

    auto issue = [&](int s, int buf) {
        int k0 = s << 5;
        cp16(&As2[buf][aRow * LASW32 + aJ * 4],
             A + (size_t)(rowBase + aRow) * sA + k0 + aJ * 8);
        const uint32_t* Bw = (const uint32_t*)B;
#pragma unroll
        for (int p = 0; p < 4; p++) {
            int r = bR + p * 4;
            cp16(&Bs2[buf][r * LBSW32 + bC],
                 Bw + (size_t)(s * 16 + r) * 256 + bC);
        }
    };

    issue(0, 0);
    asm volatile("cp.async.commit_group;\n");

    int buf = 0;
    for (int s = 0; s < NS; s++) {
        if (s + 1 < NS) {
            issue(s + 1, buf ^ 1);
            asm volatile("cp.async.commit_group;\n");
            asm volatile("cp.async.wait_group 1;\n");
        } else {
            asm volatile("cp.async.wait_group 0;\n");
        }
        __syncthreads();

        const uint32_t* AsB = As2[buf];
        const uint32_t* BsB = Bs2[buf];
#pragma unroll
        for (int ks = 0; ks < 2; ks++) {
            uint32_t af[2][4];
#pragma unroll
            for (int mt = 0; mt < 2; mt++) {
                int m = wm0 + mt * 16;
                af[mt][0] = AsB[(m + g    ) * LASW32 + ks * 8 + q    ];
                af[mt][1] = AsB[(m + g + 8) * LASW32 + ks * 8 + q    ];
                af[mt][2] = AsB[(m + g    ) * LASW32 + ks * 8 + q + 4];
                af[mt][3] = AsB[(m + g + 8) * LASW32 + ks * 8 + q + 4];
            }
            uint32_t bf[8][2];
#pragma unroll
            for (int nt = 0; nt < 8; nt++) {
                int n = wn0 + nt * 8 + g;
                bf[nt][0] = BsB[(ks * 8 + q    ) * LBSW32 + n];
                bf[nt][1] = BsB[(ks * 8 + q + 4) * LBSW32 + n];
            }
#pragma unroll
            for (int mt = 0; mt < 2; mt++)
#pragma unroll
                for (int nt = 0; nt < 8; nt++) {
                    asm volatile(
                        "mma.sync.aligned.m16n8k16.row.col.f32.f16.f16.f32 "
                        "{%0,%1,%2,%3}, {%4,%5,%6,%7}, {%8,%9}, {%0,%1,%2,%3};\n"
                        : "+f"(acc[mt][nt][0]), "+f"(acc[mt][nt][1]),
                          "+f"(acc[mt][nt][2]), "+f"(acc[mt][nt][3])
                        : "r"(af[mt][0]), "r"(af[mt][1]), "r"(af[mt][2]), "r"(af[mt][3]),
                          "r"(bf[nt][0]), "r"(bf[nt][1]));
                }
        }
        buf ^= 1;
        __syncthreads();
    }

    // ---- LayerNorm epilogue ----
#pragma unroll
    for (int mt = 0; mt < 2; mt++) {
#pragma unroll
        for (int hr = 0; hr < 2; hr++) {
            int rl = wm0 + mt * 16 + hr * 8 + g;
            float s1 = 0.0f, s2 = 0.0f;
#pragma unroll
            for (int nt = 0; nt < 8; nt++) {
                float v0 = acc[mt][nt][hr * 2], v1 = acc[mt][nt][hr * 2 + 1];
                s1 += v0 + v1;
                s2 += v0 * v0 + v1 * v1;
            }
            s1 += __shfl_xor_sync(0xffffffffu, s1, 1);
            s1 += __shfl_xor_sync(0xffffffffu, s1, 2);
            s2 += __shfl_xor_sync(0xffffffffu, s2, 1);
            s2 += __shfl_xor_sync(0xffffffffu, s2, 2);
            if (q == 0) {
                atomicAdd(&srs[rl], s1);
                atomicAdd(&ssq[rl], s2);
            }
        }
    }
    __syncthreads();

#pragma unroll
    for (int mt = 0; mt < 2; mt++) {
#pragma unroll
        for (int hr = 0; hr < 2; hr++) {
            int rl = wm0 + mt * 16 + hr * 8 + g;
            int row = rowBase + rl;
            float mu = srs[rl] * (1.0f / 256.0f);
            float var = ssq[rl] * (1.0f / 256.0f) - mu * mu;
            float rstd = rsqrtf(var + 1e-5f);
#pragma unroll
            for (int nt = 0; nt < 8; nt++) {
                int col = wn0 + nt * 8 + 2 * q;
                float v0 = (acc[mt][nt][hr * 2]     - mu) * rstd * sg[col]     + sb[col];
                float v1 = (acc[mt][nt][hr * 2 + 1] - mu) * rstd * sg[col + 1] + sb[col + 1];
                size_t o = (size_t)row * 256 + col;
                if (residual) {
                    float2 f = *(float2*)(F0 + o);
                    f.x += v0; f.y += v1;
                    *(float2*)(F0 + o) = f;
                    *(__half2*)(F0h + o) = __floats2half2_rn(f.x, f.y);
                } else {
                    *(__half2*)(OutH + o) = __floats2half2_rn(v0, v1);
                }
            }
        }
    }
}

// ---------------- KV = sum_s K[s,d]*v[s,e], Ksum per (n,h); QKV layout stride 768 ----------------
#define KV_CHUNKS 20
#define KV_SC (LL / KV_CHUNKS)
__global__ void kv_reduce_kernel(const __half* __restrict__ QKV,
                                 float* __restrict__ KV, float* __restrict__ KS) {
    int nh = blockIdx.x;
    int n = nh >> 3, h = nh & 7;
    int t = threadIdx.x;
    int d = t & 31;
    int eg = t >> 5;
    int s0 = blockIdx.y * KV_SC;
    float a0 = 0, a1 = 0, a2 = 0, a3 = 0, ks = 0;
    for (int s = s0; s < s0 + KV_SC; s++) {
        size_t rowb = (size_t)(n * LL + s) * 768 + h * HDD;
        float kd = __half2float(QKV[rowb + 256 + d]);
        const __half2* vp = (const __half2*)(QKV + rowb + 512 + eg * 4);
        float2 f0 = __half22float2(vp[0]);
        float2 f1 = __half22float2(vp[1]);
        a0 = fmaf(kd, f0.x, a0);
        a1 = fmaf(kd, f0.y, a1);
        a2 = fmaf(kd, f1.x, a2);
        a3 = fmaf(kd, f1.y, a3);
        ks += kd;
    }
    float* kvp = KV + ((size_t)nh * HDD + d) * HDD + eg * 4;
    atomicAdd(kvp + 0, a0);
    atomicAdd(kvp + 1, a1);
    atomicAdd(kvp + 2, a2);
    atomicAdd(kvp + 3, a3);
    if (eg == 0) atomicAdd(KS + nh * HDD + d, ks);
}

// ---------------- attn: Q region of QKV (stride 768) updated in place ----------------
#define AT_CHUNKS 40
#define AT_RPB (LL / AT_CHUNKS)
__global__ void attn_apply_kernel(__half* __restrict__ QKV, const float* __restrict__ KV,
                                  const float* __restrict__ KS) {
    __shared__ float kvs[32][33];
    __shared__ float kss[32];
    int n = blockIdx.z, h = blockIdx.y;
    int nh = n * NHD + h;
    int t = threadIdx.x, lane = t & 31, w = t >> 5;
    for (int i = t; i < 1024; i += 256) kvs[i >> 5][i & 31] = KV[(size_t)nh * 1024 + i];
    if (t < 32) kss[t] = KS[nh * 32 + t];
    __syncthreads();
    int l0 = blockIdx.x * AT_RPB + w * (AT_RPB / 8);
    for (int r = 0; r < AT_RPB / 8; r++) {
        int l = l0 + r;
        size_t base = (size_t)(n * LL + l) * 768 + h * HDD;
        float qd = __half2float(QKV[base + lane]);
        float zs = qd * kss[lane];
#pragma unroll
        for (int o = 16; o; o >>= 1) zs += __shfl_xor_sync(0xffffffffu, zs, o);
        float z = 1.0f / (zs + 1e-6f);
        float acc = 0.0f;
#pragma unroll
        for (int d = 0; d < 32; d++) {
            float qv = __shfl_sync(0xffffffffu, qd, d);
            acc = fmaf(qv, kvs[d][lane], acc);
        }
        QKV[base + lane] = __float2half_rn(acc * z);
    }
}

// ---------------- launch ----------------
extern "C" void kernel_launch(void* const* d_in, const int* in_sizes, int n_in,
                              void* d_out, int out_size) {
    const float* feat0 = (const float*)d_in[0];
    const float* feat1 = (const float*)d_in[1];
    const float* Wq = (const float*)d_in[2];
    const float* Wk = (const float*)d_in[3];
    const float* Wv = (const float*)d_in[4];
    const float* Wm = (const float*)d_in[5];
    const float* W1 = (const float*)d_in[6];
    const float* W2 = (const float*)d_in[7];
    const float* g1 = (const float*)d_in[8];
    const float* b1 = (const float*)d_in[9];
    const float* g2 = (const float*)d_in[10];
    const float* b2 = (const float*)d_in[11];

    float *F0, *KVS, *PE;
    __half *F0h, *F1h, *QKVh, *Mh, *Hh;
    __half *wQKV, *wM, *w1p, *w2p;
    cudaGetSymbolAddress((void**)&F0,   g_F0);
    cudaGetSymbolAddress((void**)&KVS,  g_KVS);
    cudaGetSymbolAddress((void**)&PE,   g_PE);
    cudaGetSymbolAddress((void**)&F0h,  g_F0h);
    cudaGetSymbolAddress((void**)&F1h,  g_F1h);
    cudaGetSymbolAddress((void**)&QKVh, g_QKVh);
    cudaGetSymbolAddress((void**)&Mh,   g_Mh);
    cudaGetSymbolAddress((void**)&Hh,   g_Hh);
    cudaGetSymbolAddress((void**)&wQKV, g_Wqkv);
    cudaGetSymbolAddress((void**)&wM,   g_WmH);
    cudaGetSymbolAddress((void**)&w1p,  g_W1H);
    cudaGetSymbolAddress((void**)&w2p,  g_W2H);
    float* KV = KVS;
    float* KS = KVS + KVS_KV_SZ;

    weight_prep_kernel<<<(2 * 2 * CD * CD + 255) / 256, 256>>>(Wq, Wk, Wv, Wm, W1, W2);
    pe_precompute_kernel<<<(CD * LL + 255) / 256, 256>>>(PE);

    dim3 tb(32, 8);
    dim3 tg(LL / 32, CD / 32, NB);
    build_pe_kernel<<<tg, tb>>>(feat0, PE, F0, F0h);
    build_pe_kernel<<<tg, tb>>>(feat1, PE, nullptr, F1h);

    dim3 ggQKV(6, MR / 128);   // N=768
    dim3 gg(CD / 128, MR / 128);
    const int GLN = MR / 64;

    for (int i = 0; i < 2; i++) {
        const __half* wqkv = wQKV + (size_t)i * CD * 3 * CD;
        const __half* wm = wM + (size_t)i * CD * CD;
        const __half* w1 = w1p + (size_t)i * 2 * CD * CD;
        const __half* w2 = w2p + (size_t)i * CD * CD;

        // fused Q|K|V projection: QKVh[MR][768]
        hgemm_kernel<<<ggQKV, 256>>>(F0h, F1h, wqkv, QKVh,
                                     MR, CD, CD, 3 * CD, EPI_QKV, 1, 1);

        cudaMemsetAsync(KVS, 0, sizeof(float) * NB * NHD * (HDD * HDD + HDD), 0);
        kv_reduce_kernel<<<dim3(NB * NHD, KV_CHUNKS), 256>>>(QKVh, KV, KS);

        // attention apply in place on Q region
        attn_apply_kernel<<<dim3(AT_CHUNKS, NHD, NB), 256>>>(QKVh, KV, KS);

        // merge + LN1 fused: Mh = fp16( LN(Q @ Wm) )   (A stride 768)
        hgemm_ln_kernel<<<GLN, 256>>>(QKVh, 768, wm, Mh, nullptr, nullptr,
                                      g1 + i * CD, b1 + i * CD, 0);

        // FFN1: relu([F0h|Mh] @ W1) -> Hh (fp16)
        hgemm_kernel<<<gg, 256>>>(F0h, Mh, w1, Hh, MR, 2 * CD, CD, CD, EPI_RELU, 1, 0);

        // FFN2 + LN2 + residual fused: F0 += LN(Hh @ W2); F0h = fp16(F0)
        hgemm_ln_kernel<<<GLN, 256>>>(Hh, 256, w2, nullptr, F0, F0h,
                                      g2 + i * CD, b2 + i * CD, 1);
    }

    unbuild_kernel<<<tg, tb>>>(F0, (float*)d_out);
}